// round 10
// baseline (speedup 1.0000x reference)
#include <cuda_runtime.h>
#include <cuda_bf16.h>
#include <cuda_fp16.h>
#include <cstdint>

#define NN 20000
#define EE 320000
#define DD 128
#define LL 5
#define EVV 5
#define BN_EPS 1e-5f
#define GRID 105
#define TPB 512
#define BM 192
#define MPAD (GRID * BM)   // 20160

// ---------------- device scratch ----------------
__device__ uint4 g_hh[NN * 32];        // [node][featgrp]: {t1 4 halves, t2 4 halves}
__device__ float g_Y1[NN * DD];
__device__ float g_Y2[NN * DD];
__device__ __nv_bfloat16 g_A2hi[MPAD * DD];
__device__ __nv_bfloat16 g_A2lo[MPAD * DD];
__device__ __nv_bfloat16 g_Whi[2 * LL * DD * DD];
__device__ __nv_bfloat16 g_Wlo[2 * LL * DD * DD];
__device__ int   g_deg[NN];
__device__ int   g_off[NN + 1];
__device__ int   g_cur[NN];
__device__ int   g_pack[EE];
__device__ float g_sumL[LL * 2 * DD];
__device__ float g_sqL[LL * 2 * DD];
__device__ unsigned g_bars[16];
__device__ unsigned g_done;

// ---------------- smem layout (dynamic) ----------------
#define SA_HI 0
#define SA_LO 49152
#define SW_HI 98304
#define SW_LO 131072
#define S_ET  163840
#define SM_TOTAL (163840 + 5120)   // 168960

// ---------------- PTX helpers ----------------
__device__ __forceinline__ uint32_t smem_u32(const void* p) {
    uint32_t a;
    asm("{ .reg .u64 t; cvta.to.shared.u64 t, %1; cvt.u32.u64 %0, t; }" : "=r"(a) : "l"(p));
    return a;
}
__device__ __forceinline__ void ldsm4(uint32_t* r, uint32_t addr) {
    asm volatile("ldmatrix.sync.aligned.m8n8.x4.shared.b16 {%0,%1,%2,%3}, [%4];"
                 : "=r"(r[0]), "=r"(r[1]), "=r"(r[2]), "=r"(r[3]) : "r"(addr));
}
__device__ __forceinline__ void mma16816(float* d, const uint32_t* a, const uint32_t* b) {
    asm volatile(
        "mma.sync.aligned.m16n8k16.row.col.f32.bf16.bf16.f32 "
        "{%0,%1,%2,%3}, {%4,%5,%6,%7}, {%8,%9}, {%0,%1,%2,%3};"
        : "+f"(d[0]), "+f"(d[1]), "+f"(d[2]), "+f"(d[3])
        : "r"(a[0]), "r"(a[1]), "r"(a[2]), "r"(a[3]), "r"(b[0]), "r"(b[1]));
}
__device__ __forceinline__ void cp16(uint32_t dst, const void* src) {
    asm volatile("cp.async.cg.shared.global [%0], [%1], 16;" :: "r"(dst), "l"(src));
}
__device__ __forceinline__ void cp_commit() {
    asm volatile("cp.async.commit_group;" ::: "memory");
}
__device__ __forceinline__ void cp_wait0() {
    asm volatile("cp.async.wait_group 0;" ::: "memory");
}

__device__ __forceinline__ void grid_barrier(int k) {
    __syncthreads();
    if (threadIdx.x == 0) {
        __threadfence();
        atomicAdd(&g_bars[k], 1u);
        while (*(volatile unsigned*)&g_bars[k] < (unsigned)GRID) __nanosleep(64);
    }
    __syncthreads();
}

// ---------------- small helpers ----------------
__device__ __forceinline__ float4 f4s(float s, float4 a) {
    return make_float4(s * a.x, s * a.y, s * a.z, s * a.w);
}
__device__ __forceinline__ void split4(float4 r, uint2* hi, uint2* lo) {
    __nv_bfloat16 hx = __float2bfloat16(r.x), hy = __float2bfloat16(r.y);
    __nv_bfloat16 hz = __float2bfloat16(r.z), hw = __float2bfloat16(r.w);
    __nv_bfloat16 lx = __float2bfloat16(r.x - __bfloat162float(hx));
    __nv_bfloat16 ly = __float2bfloat16(r.y - __bfloat162float(hy));
    __nv_bfloat16 lz = __float2bfloat16(r.z - __bfloat162float(hz));
    __nv_bfloat16 lw = __float2bfloat16(r.w - __bfloat162float(hw));
    hi->x = (uint32_t)__bfloat16_as_ushort(hx) | ((uint32_t)__bfloat16_as_ushort(hy) << 16);
    hi->y = (uint32_t)__bfloat16_as_ushort(hz) | ((uint32_t)__bfloat16_as_ushort(hw) << 16);
    lo->x = (uint32_t)__bfloat16_as_ushort(lx) | ((uint32_t)__bfloat16_as_ushort(ly) << 16);
    lo->y = (uint32_t)__bfloat16_as_ushort(lz) | ((uint32_t)__bfloat16_as_ushort(lw) << 16);
}
__device__ __forceinline__ uint32_t packh2(float a, float b) {
    __half2 h = __floats2half2_rn(a, b);
    return *(uint32_t*)&h;
}

// GEMM over smem tiles: 16 warps, 4m x 4n, warp tile 48x32, M=192 N=128 K=3x128
__device__ __forceinline__ void gemm_phase(char* smem, uint32_t sbase, float* Y,
                                           const float* bp, float* gsum, float* gsq,
                                           int row0, int tid) {
    int wid = tid >> 5, lane = tid & 31;
    int wm = wid & 3, wn = wid >> 2;
    int grp = lane >> 3, r8 = lane & 7;
    int a_row0 = wm * 48 + (grp & 1) * 8 + r8;
    int b_row0 = wn * 32 + (grp >> 1) * 8 + r8;
    int kselA = grp >> 1, kselB = grp & 1;

    float acc[3][4][4];
#pragma unroll
    for (int i = 0; i < 3; i++)
#pragma unroll
        for (int j = 0; j < 4; j++)
#pragma unroll
            for (int q = 0; q < 4; q++) acc[i][j][q] = 0.f;

#pragma unroll
    for (int p = 0; p < 3; p++) {
        uint32_t Ab = sbase + ((p == 2) ? SA_LO : SA_HI);
        uint32_t Bb = sbase + ((p == 1) ? SW_LO : SW_HI);
#pragma unroll
        for (int ks = 0; ks < 8; ks++) {
            uint32_t af[3][4], bf[2][4];
            uint32_t aoff = (uint32_t)(((ks * 2 + kselA) ^ r8) << 4);
#pragma unroll
            for (int i = 0; i < 3; i++)
                ldsm4(af[i], Ab + (uint32_t)(a_row0 + i * 16) * 256u + aoff);
            uint32_t boff = (uint32_t)(((ks * 2 + kselB) ^ r8) << 4);
            ldsm4(bf[0], Bb + (uint32_t)b_row0 * 256u + boff);
            ldsm4(bf[1], Bb + (uint32_t)(b_row0 + 16) * 256u + boff);
#pragma unroll
            for (int i = 0; i < 3; i++)
#pragma unroll
                for (int j = 0; j < 4; j++)
                    mma16816(acc[i][j], af[i], &bf[j >> 1][(j & 1) * 2]);
        }
    }

    int qr = lane >> 2, qc = lane & 3;
#pragma unroll
    for (int j = 0; j < 4; j++) {
        int c0 = wn * 32 + j * 8 + qc * 2;
        float bb0 = bp[c0], bb1 = bp[c0 + 1];
        float s0 = 0.f, s1 = 0.f, q0 = 0.f, q1 = 0.f;
#pragma unroll
        for (int i = 0; i < 3; i++) {
#pragma unroll
            for (int h = 0; h < 2; h++) {
                int m = row0 + wm * 48 + i * 16 + qr + h * 8;
                float v0 = acc[i][j][h * 2 + 0] + bb0;
                float v1 = acc[i][j][h * 2 + 1] + bb1;
                if (m < NN) {
                    *(float2*)&Y[m * DD + c0] = make_float2(v0, v1);
                    s0 += v0; s1 += v1;
                    q0 += v0 * v0; q1 += v1 * v1;
                }
            }
        }
#pragma unroll
        for (int off = 4; off < 32; off <<= 1) {
            s0 += __shfl_xor_sync(0xffffffffu, s0, off);
            s1 += __shfl_xor_sync(0xffffffffu, s1, off);
            q0 += __shfl_xor_sync(0xffffffffu, q0, off);
            q1 += __shfl_xor_sync(0xffffffffu, q1, off);
        }
        if (qr == 0) {
            atomicAdd(&gsum[c0], s0);
            atomicAdd(&gsum[c0 + 1], s1);
            atomicAdd(&gsq[c0], q0);
            atomicAdd(&gsq[c0 + 1], q1);
        }
    }
}

// ---------------- the persistent mega-kernel ----------------
__global__ __launch_bounds__(TPB, 1) void k_mega(
    const int* __restrict__ x, const int* __restrict__ ei, const int* __restrict__ ea,
    const float* __restrict__ ne1, const float* __restrict__ ne2,
    const float* __restrict__ eemb, const float* __restrict__ eps,
    const float* __restrict__ Wfull, const float* __restrict__ bfull,
    const float* __restrict__ gam, const float* __restrict__ bet,
    const float* __restrict__ cu, float* __restrict__ out)
{
    extern __shared__ char smem[];
    uint32_t sbase = smem_u32(smem);
    __shared__ int s_wsum[16];
    __shared__ int s_carry;

    int tid = threadIdx.x, bid = blockIdx.x;
    int gtid = bid * TPB + tid;
    const int GT = GRID * TPB;

    // ---- P0: zero deg/stats, W conv, node encode ----
    for (int i = gtid; i < NN; i += GT) g_deg[i] = 0;
    for (int i = gtid; i < LL * 2 * DD; i += GT) { g_sumL[i] = 0.f; g_sqL[i] = 0.f; }
    for (int i = gtid; i < 2 * LL * DD * DD; i += GT) {
        float v = Wfull[i];
        __nv_bfloat16 h = __float2bfloat16(v);
        g_Whi[i] = h;
        g_Wlo[i] = __float2bfloat16(v - __bfloat162float(h));
    }
    for (int i = gtid; i < NN * 32; i += GT) {
        int n = i >> 5, c = i & 31;
        int xv = __ldg(&x[n]);
        float4 a = __ldg((const float4*)ne1 + xv * 32 + c);
        float4 b2 = __ldg((const float4*)ne2 + xv * 32 + c);
        uint4 u;
        u.x = packh2(a.x, a.y); u.y = packh2(a.z, a.w);
        u.z = packh2(b2.x, b2.y); u.w = packh2(b2.z, b2.w);
        g_hh[n * 32 + c] = u;
    }
    grid_barrier(0);

    // ---- P1: hist ----
    for (int e = gtid; e < EE; e += GT)
        atomicAdd(&g_deg[__ldg(&ei[EE + e])], 1);
    grid_barrier(1);

    // ---- P2: scan (block 0) ----
    if (bid == 0) {
        int lane = tid & 31, w = tid >> 5;
        if (tid == 0) { s_carry = 0; g_off[0] = 0; }
        __syncthreads();
        for (int base = 0; base < NN; base += TPB) {
            int carry = s_carry;
            int i = base + tid;
            int v = (i < NN) ? __ldcg(&g_deg[i]) : 0;
            int xv2 = v;
#pragma unroll
            for (int o = 1; o < 32; o <<= 1) {
                int y = __shfl_up_sync(0xffffffffu, xv2, o);
                if (lane >= o) xv2 += y;
            }
            if (lane == 31) s_wsum[w] = xv2;
            __syncthreads();
            if (w == 0 && lane < 16) {
                int s = s_wsum[lane];
#pragma unroll
                for (int o = 1; o < 16; o <<= 1) {
                    int y = __shfl_up_sync(0xffffu, s, o);
                    if (lane >= o) s += y;
                }
                s_wsum[lane] = s;
            }
            __syncthreads();
            int incl = xv2 + (w ? s_wsum[w - 1] : 0) + carry;
            if (i < NN) { g_off[i + 1] = incl; g_cur[i] = incl - v; }
            __syncthreads();
            if (tid == TPB - 1) s_carry = incl;
            __syncthreads();
        }
    }
    grid_barrier(2);

    // ---- P3: scatter ----
    for (int e = gtid; e < EE; e += GT) {
        int d = __ldg(&ei[EE + e]);
        int p = atomicAdd(&g_cur[d], 1);
        g_pack[p] = (__ldg(&ei[e]) << 3) | __ldg(&ea[e]);
    }
    grid_barrier(3);

    // ---- layer loop ----
    int row0 = bid * BM;
    int wid = tid >> 5, lane = tid & 31;
    float4* s_et = (float4*)(smem + S_ET);
    int bar = 4;

    for (int l = 0; l < LL; l++) {
        // phase A: W1 cp.async + edge tables + gather + gemm t1 + gemm t2
        {
            const __nv_bfloat16* W1hi = g_Whi + (0 * LL + l) * DD * DD;
            const __nv_bfloat16* W1lo = g_Wlo + (0 * LL + l) * DD * DD;
            for (int i = tid; i < 2048; i += TPB) {
                int row = i >> 4, ch = i & 15;
                uint32_t so = (uint32_t)row * 256u + (uint32_t)((ch ^ (row & 7)) << 4);
                cp16(sbase + SW_HI + so, (const char*)(W1hi + (size_t)row * DD) + ch * 16);
                cp16(sbase + SW_LO + so, (const char*)(W1lo + (size_t)row * DD) + ch * 16);
            }
            cp_commit();
            const float4* et1 = (const float4*)(eemb + (0 * LL + l) * EVV * DD);
            const float4* et2 = (const float4*)(eemb + (1 * LL + l) * EVV * DD);
            for (int i = tid; i < 320; i += TPB)
                s_et[i] = (i < 160) ? __ldg(et1 + i) : __ldg(et2 + (i - 160));
            __syncthreads();

            float e1 = 1.f + __ldg(&eps[l]);
            float e2 = 1.f + __ldg(&eps[LL + l]);

            for (int r = 0; r < BM / 16; r++) {
                int row = wid * (BM / 16) + r;
                int n = row0 + row;
                float4 r1 = make_float4(0.f, 0.f, 0.f, 0.f);
                float4 r2 = make_float4(0.f, 0.f, 0.f, 0.f);
                if (n < NN) {
                    int beg = __ldg(&g_off[n]);
                    int deg = __ldg(&g_off[n + 1]) - beg;
                    for (int base = 0; base < deg; base += 32) {
                        int idx = base + lane;
                        int pk = (idx < deg) ? __ldg(&g_pack[beg + idx]) : 0;
                        int cnt = min(32, deg - base);
                        int k = 0;
                        for (; k + 4 <= cnt; k += 4) {
                            int pa[4]; uint4 u[4];
#pragma unroll
                            for (int j = 0; j < 4; j++)
                                pa[j] = __shfl_sync(0xffffffffu, pk, k + j);
#pragma unroll
                            for (int j = 0; j < 4; j++)
                                u[j] = __ldcg(&g_hh[(pa[j] >> 3) * 32 + lane]);
#pragma unroll
                            for (int j = 0; j < 4; j++) {
                                int a = pa[j] & 7;
                                float2 fa = __half22float2(*(__half2*)&u[j].x);
                                float2 fb = __half22float2(*(__half2*)&u[j].y);
                                float2 fc = __half22float2(*(__half2*)&u[j].z);
                                float2 fd = __half22float2(*(__half2*)&u[j].w);
                                float4 t1 = s_et[a * 32 + lane];
                                float4 t2 = s_et[160 + a * 32 + lane];
                                r1.x += fmaxf(fa.x + t1.x, 0.f);
                                r1.y += fmaxf(fa.y + t1.y, 0.f);
                                r1.z += fmaxf(fb.x + t1.z, 0.f);
                                r1.w += fmaxf(fb.y + t1.w, 0.f);
                                r2.x += fmaxf(fc.x + t2.x, 0.f);
                                r2.y += fmaxf(fc.y + t2.y, 0.f);
                                r2.z += fmaxf(fd.x + t2.z, 0.f);
                                r2.w += fmaxf(fd.y + t2.w, 0.f);
                            }
                        }
                        for (; k < cnt; k++) {
                            int p = __shfl_sync(0xffffffffu, pk, k);
                            int a = p & 7;
                            uint4 u = __ldcg(&g_hh[(p >> 3) * 32 + lane]);
                            float2 fa = __half22float2(*(__half2*)&u.x);
                            float2 fb = __half22float2(*(__half2*)&u.y);
                            float2 fc = __half22float2(*(__half2*)&u.z);
                            float2 fd = __half22float2(*(__half2*)&u.w);
                            float4 t1 = s_et[a * 32 + lane];
                            float4 t2 = s_et[160 + a * 32 + lane];
                            r1.x += fmaxf(fa.x + t1.x, 0.f);
                            r1.y += fmaxf(fa.y + t1.y, 0.f);
                            r1.z += fmaxf(fb.x + t1.z, 0.f);
                            r1.w += fmaxf(fb.y + t1.w, 0.f);
                            r2.x += fmaxf(fc.x + t2.x, 0.f);
                            r2.y += fmaxf(fc.y + t2.y, 0.f);
                            r2.z += fmaxf(fd.x + t2.z, 0.f);
                            r2.w += fmaxf(fd.y + t2.w, 0.f);
                        }
                    }
                    uint4 u = __ldcg(&g_hh[n * 32 + lane]);
                    float2 fa = __half22float2(*(__half2*)&u.x);
                    float2 fb = __half22float2(*(__half2*)&u.y);
                    float2 fc = __half22float2(*(__half2*)&u.z);
                    float2 fd = __half22float2(*(__half2*)&u.w);
                    r1.x += e1 * fa.x; r1.y += e1 * fa.y;
                    r1.z += e1 * fb.x; r1.w += e1 * fb.y;
                    r2.x += e2 * fc.x; r2.y += e2 * fc.y;
                    r2.z += e2 * fd.x; r2.w += e2 * fd.y;
                }
                uint2 hi, lo;
                split4(r1, &hi, &lo);
                uint32_t so = (uint32_t)row * 256u
                            + (uint32_t)(((lane >> 1) ^ (row & 7)) << 4)
                            + (uint32_t)(lane & 1) * 8u;
                *(uint2*)(smem + SA_HI + so) = hi;
                *(uint2*)(smem + SA_LO + so) = lo;
                split4(r2, &hi, &lo);
                *(uint2*)&g_A2hi[(size_t)(row0 + row) * DD + lane * 4] = hi;
                *(uint2*)&g_A2lo[(size_t)(row0 + row) * DD + lane * 4] = lo;
            }
            cp_wait0();
            __syncthreads();

            // gemm tower 1
            gemm_phase(smem, sbase, g_Y1, bfull + (0 * LL + l) * DD,
                       g_sumL + l * 2 * DD, g_sqL + l * 2 * DD, row0, tid);
            __syncthreads();

            // load A2 + W2
            const __nv_bfloat16* W2hi = g_Whi + (1 * LL + l) * DD * DD;
            const __nv_bfloat16* W2lo = g_Wlo + (1 * LL + l) * DD * DD;
            for (int i = tid; i < 3072; i += TPB) {
                int row = i >> 4, ch = i & 15;
                uint32_t so = (uint32_t)row * 256u + (uint32_t)((ch ^ (row & 7)) << 4);
                cp16(sbase + SA_HI + so,
                     (const char*)(g_A2hi + (size_t)(row0 + row) * DD) + ch * 16);
                cp16(sbase + SA_LO + so,
                     (const char*)(g_A2lo + (size_t)(row0 + row) * DD) + ch * 16);
            }
            for (int i = tid; i < 2048; i += TPB) {
                int row = i >> 4, ch = i & 15;
                uint32_t so = (uint32_t)row * 256u + (uint32_t)((ch ^ (row & 7)) << 4);
                cp16(sbase + SW_HI + so, (const char*)(W2hi + (size_t)row * DD) + ch * 16);
                cp16(sbase + SW_LO + so, (const char*)(W2lo + (size_t)row * DD) + ch * 16);
            }
            cp_commit();
            cp_wait0();
            __syncthreads();

            // gemm tower 2
            gemm_phase(smem, sbase, g_Y2, bfull + (1 * LL + l) * DD,
                       g_sumL + l * 2 * DD + DD, g_sqL + l * 2 * DD + DD, row0, tid);
        }
        grid_barrier(bar++);

        // phase B: bn_cross for own rows
        {
            const float inv = 1.f / (float)NN;
            const float* gsum = g_sumL + l * 2 * DD;
            const float* gsq = g_sqL + l * 2 * DD;
            int last = (l == LL - 1);
            float c00 = __ldg(&cu[l * 4 + 0]), c01 = __ldg(&cu[l * 4 + 1]);
            float c10 = __ldg(&cu[l * 4 + 2]), c11 = __ldg(&cu[l * 4 + 3]);
            for (int idx = tid; idx < BM * 32; idx += TPB) {
                int n = row0 + (idx >> 5);
                if (n >= NN) continue;
                int c4 = idx & 31, f = c4 * 4;

                float4 s1 = __ldcg((const float4*)&gsum[f]);
                float4 q1 = __ldcg((const float4*)&gsq[f]);
                float4 s2 = __ldcg((const float4*)&gsum[DD + f]);
                float4 q2 = __ldcg((const float4*)&gsq[DD + f]);
                float4 mu1 = f4s(inv, s1), mu2 = f4s(inv, s2);
                float4 rs1 = make_float4(rsqrtf(q1.x * inv - mu1.x * mu1.x + BN_EPS),
                                         rsqrtf(q1.y * inv - mu1.y * mu1.y + BN_EPS),
                                         rsqrtf(q1.z * inv - mu1.z * mu1.z + BN_EPS),
                                         rsqrtf(q1.w * inv - mu1.w * mu1.w + BN_EPS));
                float4 rs2 = make_float4(rsqrtf(q2.x * inv - mu2.x * mu2.x + BN_EPS),
                                         rsqrtf(q2.y * inv - mu2.y * mu2.y + BN_EPS),
                                         rsqrtf(q2.z * inv - mu2.z * mu2.z + BN_EPS),
                                         rsqrtf(q2.w * inv - mu2.w * mu2.w + BN_EPS));
                float4 g1 = __ldg((const float4*)&gam[(0 * LL + l) * DD + f]);
                float4 b1 = __ldg((const float4*)&bet[(0 * LL + l) * DD + f]);
                float4 g2 = __ldg((const float4*)&gam[(1 * LL + l) * DD + f]);
                float4 b2 = __ldg((const float4*)&bet[(1 * LL + l) * DD + f]);

                float4 y1 = *(const float4*)&g_Y1[n * DD + f];
                float4 y2 = *(const float4*)&g_Y2[n * DD + f];

                y1.x = (y1.x - mu1.x) * rs1.x * g1.x + b1.x;
                y1.y = (y1.y - mu1.y) * rs1.y * g1.y + b1.y;
                y1.z = (y1.z - mu1.z) * rs1.z * g1.z + b1.z;
                y1.w = (y1.w - mu1.w) * rs1.w * g1.w + b1.w;
                y2.x = (y2.x - mu2.x) * rs2.x * g2.x + b2.x;
                y2.y = (y2.y - mu2.y) * rs2.y * g2.y + b2.y;
                y2.z = (y2.z - mu2.z) * rs2.z * g2.z + b2.z;
                y2.w = (y2.w - mu2.w) * rs2.w * g2.w + b2.w;

                if (!last) {
                    y1.x = fmaxf(y1.x, 0.f); y1.y = fmaxf(y1.y, 0.f);
                    y1.z = fmaxf(y1.z, 0.f); y1.w = fmaxf(y1.w, 0.f);
                    y2.x = fmaxf(y2.x, 0.f); y2.y = fmaxf(y2.y, 0.f);
                    y2.z = fmaxf(y2.z, 0.f); y2.w = fmaxf(y2.w, 0.f);
                }
                float4 n1 = make_float4(c00 * y1.x + c01 * y2.x, c00 * y1.y + c01 * y2.y,
                                        c00 * y1.z + c01 * y2.z, c00 * y1.w + c01 * y2.w);
                float4 n2 = make_float4(c10 * n1.x + c11 * y2.x, c10 * n1.y + c11 * y2.y,
                                        c10 * n1.z + c11 * y2.z, c10 * n1.w + c11 * y2.w);
                if (last) {
                    ((float4*)out)[n * 32 + c4] = n1;
                    ((float4*)out)[NN * 32 + n * 32 + c4] = n2;
                } else {
                    uint4 u;
                    u.x = packh2(n1.x, n1.y); u.y = packh2(n1.z, n1.w);
                    u.z = packh2(n2.x, n2.y); u.w = packh2(n2.z, n2.w);
                    g_hh[n * 32 + c4] = u;
                }
            }
        }
        if (l < LL - 1) grid_barrier(bar++);
    }

    // ---- done protocol: reset barrier state for next launch ----
    __syncthreads();
    if (tid == 0) {
        __threadfence();
        atomicAdd(&g_done, 1u);
        if (bid == 0) {
            while (*(volatile unsigned*)&g_done < (unsigned)GRID) __nanosleep(64);
            for (int k = 0; k < 16; k++) g_bars[k] = 0;
            g_done = 0;
            __threadfence();
        }
    }
}

// ---------------- launch ----------------
extern "C" void kernel_launch(void* const* d_in, const int* in_sizes, int n_in,
                              void* d_out, int out_size) {
    const int* x = (const int*)d_in[0];
    const int* ei = (const int*)d_in[1];
    const int* ea = (const int*)d_in[2];
    const float* ne1 = (const float*)d_in[3];
    const float* ne2 = (const float*)d_in[4];
    const float* eemb = (const float*)d_in[5];
    const float* eps = (const float*)d_in[6];
    const float* W = (const float*)d_in[7];
    const float* b = (const float*)d_in[8];
    const float* gam = (const float*)d_in[9];
    const float* bet = (const float*)d_in[10];
    const float* cu = (const float*)d_in[11];
    float* out = (float*)d_out;

    static int smem_set = 0;
    if (!smem_set) {
        cudaFuncSetAttribute(k_mega, cudaFuncAttributeMaxDynamicSharedMemorySize,
                             SM_TOTAL);
        smem_set = 1;
    }

    k_mega<<<GRID, TPB, SM_TOTAL>>>(x, ei, ea, ne1, ne2, eemb, eps, W, b,
                                    gam, bet, cu, out);
}

// round 12
// speedup vs baseline: 1.3453x; 1.3453x over previous
#include <cuda_runtime.h>
#include <cuda_bf16.h>
#include <cuda_fp16.h>
#include <cstdint>

#define NN 20000
#define EE 320000
#define DD 128
#define LL 5
#define EVV 5
#define BN_EPS 1e-5f
#define MPAD 20096   // 157 * 128

// ---------------- device scratch (no allocation allowed) ----------------
__device__ uint2 g_hh[NN * 64];        // fp16 h, [node][tower][128]: uint2 = 4 halves
__device__ float g_Y1[NN * DD];
__device__ float g_Y2[NN * DD];
__device__ __half g_A1hi[MPAD * DD];
__device__ __half g_A1lo[MPAD * DD];
__device__ __half g_A2hi[MPAD * DD];
__device__ __half g_A2lo[MPAD * DD];
__device__ __half g_Wh[2 * LL * DD * DD];
__device__ int   g_deg[NN];
__device__ int   g_off[NN + 1];
__device__ int   g_cur[NN];
__device__ int   g_pack[EE];     // (src << 3) | attr
__device__ float g_sumL[LL * 2 * DD];
__device__ float g_sqL[LL * 2 * DD];

// ---------------- PTX helpers ----------------
__device__ __forceinline__ uint32_t smem_u32(const void* p) {
    uint32_t a;
    asm("{ .reg .u64 t; cvta.to.shared.u64 t, %1; cvt.u32.u64 %0, t; }" : "=r"(a) : "l"(p));
    return a;
}
__device__ __forceinline__ void ldsm4(uint32_t* r, uint32_t addr) {
    asm volatile("ldmatrix.sync.aligned.m8n8.x4.shared.b16 {%0,%1,%2,%3}, [%4];"
                 : "=r"(r[0]), "=r"(r[1]), "=r"(r[2]), "=r"(r[3]) : "r"(addr));
}
__device__ __forceinline__ void mma16816h(float* d, const uint32_t* a, const uint32_t* b) {
    asm volatile(
        "mma.sync.aligned.m16n8k16.row.col.f32.f16.f16.f32 "
        "{%0,%1,%2,%3}, {%4,%5,%6,%7}, {%8,%9}, {%0,%1,%2,%3};"
        : "+f"(d[0]), "+f"(d[1]), "+f"(d[2]), "+f"(d[3])
        : "r"(a[0]), "r"(a[1]), "r"(a[2]), "r"(a[3]), "r"(b[0]), "r"(b[1]));
}
__device__ __forceinline__ void cp16(uint32_t dst, const void* src) {
    asm volatile("cp.async.cg.shared.global [%0], [%1], 16;" :: "r"(dst), "l"(src));
}
__device__ __forceinline__ void cp_commit_wait() {
    asm volatile("cp.async.commit_group;" ::: "memory");
    asm volatile("cp.async.wait_group 0;" ::: "memory");
}

// ---------------- small vector helpers ----------------
__device__ __forceinline__ float4 f4relu(float4 a) {
    return make_float4(fmaxf(a.x, 0.f), fmaxf(a.y, 0.f), fmaxf(a.z, 0.f), fmaxf(a.w, 0.f));
}
__device__ __forceinline__ float4 f4add(float4 a, float4 b) {
    return make_float4(a.x + b.x, a.y + b.y, a.z + b.z, a.w + b.w);
}
__device__ __forceinline__ float4 f4s(float s, float4 a) {
    return make_float4(s * a.x, s * a.y, s * a.z, s * a.w);
}
__device__ __forceinline__ float4 f4sma(float s, float4 a, float4 b) {
    return make_float4(fmaf(s, a.x, b.x), fmaf(s, a.y, b.y),
                       fmaf(s, a.z, b.z), fmaf(s, a.w, b.w));
}
__device__ __forceinline__ float4 h2f4(uint2 u) {
    float2 fa = __half22float2(*(__half2*)&u.x);
    float2 fb = __half22float2(*(__half2*)&u.y);
    return make_float4(fa.x, fa.y, fb.x, fb.y);
}
__device__ __forceinline__ uint2 f4h(float4 v) {
    __half2 a = __floats2half2_rn(v.x, v.y);
    __half2 b = __floats2half2_rn(v.z, v.w);
    uint2 r;
    r.x = *(uint32_t*)&a;
    r.y = *(uint32_t*)&b;
    return r;
}
// fp16 hi/lo split of a float4
__device__ __forceinline__ void split4h(float4 r, uint2* hi, uint2* lo) {
    __half hx = __float2half_rn(r.x), hy = __float2half_rn(r.y);
    __half hz = __float2half_rn(r.z), hw = __float2half_rn(r.w);
    __half lx = __float2half_rn(r.x - __half2float(hx));
    __half ly = __float2half_rn(r.y - __half2float(hy));
    __half lz = __float2half_rn(r.z - __half2float(hz));
    __half lw = __float2half_rn(r.w - __half2float(hw));
    hi->x = (uint32_t)__half_as_ushort(hx) | ((uint32_t)__half_as_ushort(hy) << 16);
    hi->y = (uint32_t)__half_as_ushort(hz) | ((uint32_t)__half_as_ushort(hw) << 16);
    lo->x = (uint32_t)__half_as_ushort(lx) | ((uint32_t)__half_as_ushort(ly) << 16);
    lo->y = (uint32_t)__half_as_ushort(lz) | ((uint32_t)__half_as_ushort(lw) << 16);
}

// ---------------- CSR build ----------------
__global__ void k_hist(const int* __restrict__ ei) {
    int e = blockIdx.x * blockDim.x + threadIdx.x;
    if (e < EE) atomicAdd(&g_deg[ei[EE + e]], 1);
}

__global__ void k_scan() {
    __shared__ int wsum[32];
    __shared__ int carry;
    int tid = threadIdx.x, lane = tid & 31, w = tid >> 5;
    if (tid == 0) { carry = 0; g_off[0] = 0; }
    __syncthreads();
    for (int base = 0; base < NN; base += 1024) {
        int i = base + tid;
        int v = (i < NN) ? g_deg[i] : 0;
        int x = v;
#pragma unroll
        for (int o = 1; o < 32; o <<= 1) {
            int y = __shfl_up_sync(0xffffffffu, x, o);
            if (lane >= o) x += y;
        }
        if (lane == 31) wsum[w] = x;
        __syncthreads();
        if (w == 0) {
            int s = wsum[lane];
#pragma unroll
            for (int o = 1; o < 32; o <<= 1) {
                int y = __shfl_up_sync(0xffffffffu, s, o);
                if (lane >= o) s += y;
            }
            wsum[lane] = s;
        }
        __syncthreads();
        int incl = x + (w ? wsum[w - 1] : 0) + carry;
        if (i < NN) { g_off[i + 1] = incl; g_cur[i] = incl - v; }
        __syncthreads();
        if (tid == 1023) carry = incl;
        __syncthreads();
    }
}

__global__ void k_scatter(const int* __restrict__ ei, const int* __restrict__ ea) {
    int e = blockIdx.x * blockDim.x + threadIdx.x;
    if (e < EE) {
        int d = ei[EE + e];
        int p = atomicAdd(&g_cur[d], 1);
        g_pack[p] = (ei[e] << 3) | ea[e];
    }
}

// ---------------- merged prologue: deg zero + stats zero + W fp16 + encode ---
__global__ void k_prep(const float* __restrict__ Wfull, const int* __restrict__ x,
                       const float* __restrict__ ne1, const float* __restrict__ ne2) {
    int i = blockIdx.x * blockDim.x + threadIdx.x;
    if (i < NN) g_deg[i] = 0;
    if (i < LL * 2 * DD) { g_sumL[i] = 0.f; g_sqL[i] = 0.f; }
    if (i < 2 * LL * DD * DD) g_Wh[i] = __float2half_rn(Wfull[i]);
    if (i < NN * 32) {
        int n = i >> 5, c = i & 31;
        int xv = x[n];
        g_hh[n * 64 + c] = f4h(((const float4*)ne1)[xv * 32 + c]);
        g_hh[n * 64 + 32 + c] = f4h(((const float4*)ne2)[xv * 32 + c]);
    }
}

// ---------------- gather aggregation: fp16 h rows, writes fp16 hi/lo A -------
__global__ __launch_bounds__(512) void k_aggregate(const float* __restrict__ eemb,
                                                   const float* __restrict__ eps_ptr,
                                                   int layer) {
    __shared__ float4 s_et[2 * EVV * 32];
    int tid = threadIdx.x;
    const float* et1 = eemb + (0 * LL + layer) * EVV * DD;
    const float* et2 = eemb + (1 * LL + layer) * EVV * DD;
    if (tid < 2 * EVV * 32) {
        if (tid < EVV * 32) s_et[tid] = ((const float4*)et1)[tid];
        else                s_et[tid] = ((const float4*)et2)[tid - EVV * 32];
    }
    __syncthreads();

    int warp = tid >> 5, lane = tid & 31;
    int n = blockIdx.x * 16 + warp;           // grid 1250 * 16 = 20000 exactly

    int beg = g_off[n], deg = g_off[n + 1] - beg;
    float4 acc1 = make_float4(0.f, 0.f, 0.f, 0.f);
    float4 acc2 = make_float4(0.f, 0.f, 0.f, 0.f);

    for (int base = 0; base < deg; base += 32) {
        int idx = base + lane;
        int pk = (idx < deg) ? __ldg(&g_pack[beg + idx]) : 0;
        int cnt = min(32, deg - base);
        int k = 0;
        for (; k + 4 <= cnt; k += 4) {
            int pa[4];
            uint2 u1[4], u2[4];
#pragma unroll
            for (int j = 0; j < 4; j++) pa[j] = __shfl_sync(0xffffffffu, pk, k + j);
#pragma unroll
            for (int j = 0; j < 4; j++) {
                int s = pa[j] >> 3;
                u1[j] = __ldcg(&g_hh[s * 64 + lane]);
                u2[j] = __ldcg(&g_hh[s * 64 + 32 + lane]);
            }
#pragma unroll
            for (int j = 0; j < 4; j++) {
                int a = pa[j] & 7;
                acc1 = f4add(acc1, f4relu(f4add(h2f4(u1[j]), s_et[a * 32 + lane])));
                acc2 = f4add(acc2, f4relu(f4add(h2f4(u2[j]), s_et[EVV * 32 + a * 32 + lane])));
            }
        }
        for (; k < cnt; k++) {
            int p = __shfl_sync(0xffffffffu, pk, k);
            int s = p >> 3, a = p & 7;
            acc1 = f4add(acc1, f4relu(f4add(h2f4(__ldcg(&g_hh[s * 64 + lane])),
                                            s_et[a * 32 + lane])));
            acc2 = f4add(acc2, f4relu(f4add(h2f4(__ldcg(&g_hh[s * 64 + 32 + lane])),
                                            s_et[EVV * 32 + a * 32 + lane])));
        }
    }
    float e1 = 1.f + eps_ptr[layer];
    float e2 = 1.f + eps_ptr[LL + layer];
    float4 o1 = h2f4(__ldcg(&g_hh[n * 64 + lane]));
    float4 o2 = h2f4(__ldcg(&g_hh[n * 64 + 32 + lane]));
    float4 r1 = f4sma(e1, o1, acc1);
    float4 r2 = f4sma(e2, o2, acc2);

    uint2 hi, lo;
    split4h(r1, &hi, &lo);
    *(uint2*)&g_A1hi[n * DD + lane * 4] = hi;
    *(uint2*)&g_A1lo[n * DD + lane * 4] = lo;
    split4h(r2, &hi, &lo);
    *(uint2*)&g_A2hi[n * DD + lane * 4] = hi;
    *(uint2*)&g_A2lo[n * DD + lane * 4] = lo;
}

// ---------------- HMMA GEMM: Y = A @ W^T + b (fp16 A hi/lo x2, fp32 acc) -----
// SMEM (96KB): Ahi | Alo | W, each 128 rows x 256B, XOR-swizzled 16B chunks
#define SM_AHI  0
#define SM_ALO  32768
#define SM_W    65536
#define SM_GEMM_TOTAL 98304

__global__ __launch_bounds__(256, 2) void k_gemm_tc(const float* __restrict__ bfull,
                                                    int layer) {
    extern __shared__ char smem[];
    uint32_t sbase = smem_u32(smem);
    int tid = threadIdx.x;
    int wid = tid >> 5, lane = tid & 31;

    int t = blockIdx.y;
    const __half* Ahi = t ? g_A2hi : g_A1hi;
    const __half* Alo = t ? g_A2lo : g_A1lo;
    const __half* Wh = g_Wh + (t * LL + layer) * DD * DD;
    float* Y = t ? g_Y2 : g_Y1;
    const float* bp = bfull + (t * LL + layer) * DD;
    int m0 = blockIdx.x * 128;

    for (int i = tid; i < 2048; i += 256) {
        int row = i >> 4, ch = i & 15;
        uint32_t so = (uint32_t)row * 256u + (uint32_t)((ch ^ (row & 7)) << 4);
        cp16(sbase + SM_AHI + so, (const char*)(Ahi + (size_t)(m0 + row) * DD) + ch * 16);
        cp16(sbase + SM_ALO + so, (const char*)(Alo + (size_t)(m0 + row) * DD) + ch * 16);
        cp16(sbase + SM_W + so, (const char*)(Wh + (size_t)row * DD) + ch * 16);
    }
    cp_commit_wait();
    __syncthreads();

    int wm = wid & 3, wn = wid >> 2;
    int grp = lane >> 3, r8 = lane & 7;
    int a_row0 = wm * 32 + (grp & 1) * 8 + r8;
    int b_row0 = wn * 64 + (grp >> 1) * 8 + r8;
    int kselA = grp >> 1;
    int kselB = grp & 1;

    float acc[2][8][4];
#pragma unroll
    for (int i = 0; i < 2; i++)
#pragma unroll
        for (int j = 0; j < 8; j++)
#pragma unroll
            for (int q = 0; q < 4; q++) acc[i][j][q] = 0.f;

#pragma unroll
    for (int p = 0; p < 2; p++) {
        uint32_t Ab = sbase + (p ? SM_ALO : SM_AHI);
        uint32_t Bb = sbase + SM_W;
#pragma unroll
        for (int ks = 0; ks < 8; ks++) {
            uint32_t af[2][4], bf[4][4];
            uint32_t aoff = (uint32_t)(((ks * 2 + kselA) ^ r8) << 4);
            ldsm4(af[0], Ab + (uint32_t)a_row0 * 256u + aoff);
            ldsm4(af[1], Ab + (uint32_t)(a_row0 + 16) * 256u + aoff);
            uint32_t boff = (uint32_t)(((ks * 2 + kselB) ^ r8) << 4);
#pragma unroll
            for (int jj = 0; jj < 4; jj++)
                ldsm4(bf[jj], Bb + (uint32_t)(b_row0 + jj * 16) * 256u + boff);
#pragma unroll
            for (int i = 0; i < 2; i++)
#pragma unroll
                for (int j = 0; j < 8; j++)
                    mma16816h(acc[i][j], af[i], &bf[j >> 1][(j & 1) * 2]);
        }
    }

    float* gsum = g_sumL + layer * 2 * DD + t * DD;
    float* gsq = g_sqL + layer * 2 * DD + t * DD;
    int qr = lane >> 2, qc = lane & 3;
#pragma unroll
    for (int j = 0; j < 8; j++) {
        int c0 = wn * 64 + j * 8 + qc * 2;
        float bb0 = bp[c0], bb1 = bp[c0 + 1];
        float s0 = 0.f, s1 = 0.f, q0 = 0.f, q1 = 0.f;
#pragma unroll
        for (int i = 0; i < 2; i++) {
#pragma unroll
            for (int h = 0; h < 2; h++) {
                int m = m0 + wm * 32 + i * 16 + qr + h * 8;
                float v0 = acc[i][j][h * 2 + 0] + bb0;
                float v1 = acc[i][j][h * 2 + 1] + bb1;
                if (m < NN) {
                    *(float2*)&Y[m * DD + c0] = make_float2(v0, v1);
                    s0 += v0; s1 += v1;
                    q0 += v0 * v0; q1 += v1 * v1;
                }
            }
        }
#pragma unroll
        for (int off = 4; off < 32; off <<= 1) {
            s0 += __shfl_xor_sync(0xffffffffu, s0, off);
            s1 += __shfl_xor_sync(0xffffffffu, s1, off);
            q0 += __shfl_xor_sync(0xffffffffu, q0, off);
            q1 += __shfl_xor_sync(0xffffffffu, q1, off);
        }
        if (qr == 0) {
            atomicAdd(&gsum[c0], s0);
            atomicAdd(&gsum[c0 + 1], s1);
            atomicAdd(&gsq[c0], q0);
            atomicAdd(&gsq[c0 + 1], q1);
        }
    }
}

// ---------------- BN + relu + cross-stitch (per node) ----------------
__global__ void k_bn_cross(const float* __restrict__ gam,
                           const float* __restrict__ bet,
                           const float* __restrict__ cu,
                           int layer, int last, float* __restrict__ out) {
    int idx = blockIdx.x * blockDim.x + threadIdx.x;
    if (idx >= NN * 32) return;
    int n = idx >> 5, c4 = idx & 31;
    int f = c4 * 4;
    const float inv = 1.f / (float)NN;
    const float* gsum = g_sumL + layer * 2 * DD;
    const float* gsq = g_sqL + layer * 2 * DD;

    float4 s1 = *(const float4*)&gsum[f];
    float4 q1 = *(const float4*)&gsq[f];
    float4 s2 = *(const float4*)&gsum[DD + f];
    float4 q2 = *(const float4*)&gsq[DD + f];

    float4 mu1 = f4s(inv, s1), mu2 = f4s(inv, s2);
    float4 rs1 = make_float4(rsqrtf(q1.x * inv - mu1.x * mu1.x + BN_EPS),
                             rsqrtf(q1.y * inv - mu1.y * mu1.y + BN_EPS),
                             rsqrtf(q1.z * inv - mu1.z * mu1.z + BN_EPS),
                             rsqrtf(q1.w * inv - mu1.w * mu1.w + BN_EPS));
    float4 rs2 = make_float4(rsqrtf(q2.x * inv - mu2.x * mu2.x + BN_EPS),
                             rsqrtf(q2.y * inv - mu2.y * mu2.y + BN_EPS),
                             rsqrtf(q2.z * inv - mu2.z * mu2.z + BN_EPS),
                             rsqrtf(q2.w * inv - mu2.w * mu2.w + BN_EPS));

    float4 g1 = *(const float4*)&gam[(0 * LL + layer) * DD + f];
    float4 b1 = *(const float4*)&bet[(0 * LL + layer) * DD + f];
    float4 g2 = *(const float4*)&gam[(1 * LL + layer) * DD + f];
    float4 b2 = *(const float4*)&bet[(1 * LL + layer) * DD + f];

    float4 y1 = ((const float4*)g_Y1)[n * 32 + c4];
    float4 y2 = ((const float4*)g_Y2)[n * 32 + c4];

    y1.x = (y1.x - mu1.x) * rs1.x * g1.x + b1.x;
    y1.y = (y1.y - mu1.y) * rs1.y * g1.y + b1.y;
    y1.z = (y1.z - mu1.z) * rs1.z * g1.z + b1.z;
    y1.w = (y1.w - mu1.w) * rs1.w * g1.w + b1.w;
    y2.x = (y2.x - mu2.x) * rs2.x * g2.x + b2.x;
    y2.y = (y2.y - mu2.y) * rs2.y * g2.y + b2.y;
    y2.z = (y2.z - mu2.z) * rs2.z * g2.z + b2.z;
    y2.w = (y2.w - mu2.w) * rs2.w * g2.w + b2.w;

    if (!last) {
        y1 = f4relu(y1);
        y2 = f4relu(y2);
    }

    float c00 = cu[layer * 4 + 0], c01 = cu[layer * 4 + 1];
    float c10 = cu[layer * 4 + 2], c11 = cu[layer * 4 + 3];

    float4 n1 = make_float4(c00 * y1.x + c01 * y2.x, c00 * y1.y + c01 * y2.y,
                            c00 * y1.z + c01 * y2.z, c00 * y1.w + c01 * y2.w);
    float4 n2 = make_float4(c10 * n1.x + c11 * y2.x, c10 * n1.y + c11 * y2.y,
                            c10 * n1.z + c11 * y2.z, c10 * n1.w + c11 * y2.w);

    if (last) {
        ((float4*)out)[n * 32 + c4] = n1;
        ((float4*)out)[NN * 32 + n * 32 + c4] = n2;
    } else {
        g_hh[n * 64 + c4] = f4h(n1);
        g_hh[n * 64 + 32 + c4] = f4h(n2);
    }
}

// ---------------- launch ----------------
extern "C" void kernel_launch(void* const* d_in, const int* in_sizes, int n_in,
                              void* d_out, int out_size) {
    const int* x = (const int*)d_in[0];
    const int* ei = (const int*)d_in[1];
    const int* ea = (const int*)d_in[2];
    const float* ne1 = (const float*)d_in[3];
    const float* ne2 = (const float*)d_in[4];
    const float* eemb = (const float*)d_in[5];
    const float* eps = (const float*)d_in[6];
    const float* W = (const float*)d_in[7];
    const float* b = (const float*)d_in[8];
    const float* gam = (const float*)d_in[9];
    const float* bet = (const float*)d_in[10];
    const float* cu = (const float*)d_in[11];
    float* out = (float*)d_out;

    static int smem_set = 0;
    if (!smem_set) {
        cudaFuncSetAttribute(k_gemm_tc, cudaFuncAttributeMaxDynamicSharedMemorySize,
                             SM_GEMM_TOTAL);
        smem_set = 1;
    }

    k_prep<<<(NN * 32 + 255) / 256, 256>>>(W, x, ne1, ne2);
    k_hist<<<(EE + 255) / 256, 256>>>(ei);
    k_scan<<<1, 1024>>>();
    k_scatter<<<(EE + 255) / 256, 256>>>(ei, ea);

    for (int l = 0; l < LL; l++) {
        k_aggregate<<<NN / 16, 512>>>(eemb, eps, l);
        dim3 gg((NN + 127) / 128, 2);
        k_gemm_tc<<<gg, 256, SM_GEMM_TOTAL>>>(b, l);
        k_bn_cross<<<(NN * 32 + 255) / 256, 256>>>(gam, bet, cu, l, (l == LL - 1) ? 1 : 0, out);
    }
}

// round 13
// speedup vs baseline: 1.4502x; 1.0780x over previous
#include <cuda_runtime.h>
#include <cuda_bf16.h>
#include <cuda_fp16.h>
#include <cstdint>

#define NN 20000
#define EE 320000
#define DD 128
#define LL 5
#define EVV 5
#define BN_EPS 1e-5f
#define MPAD 20096   // padded rows for GEMM tiles (zero-init tail is benign)

// ---------------- device scratch (no allocation allowed) ----------------
__device__ uint4 g_hh[NN * 32];        // fp16 h, [node][fg]: {t1 f0..3, t2 f0..3}
__device__ float g_Y1[NN * DD];
__device__ float g_Y2[NN * DD];
__device__ __nv_bfloat16 g_A1hi[MPAD * DD];
__device__ __nv_bfloat16 g_A1lo[MPAD * DD];
__device__ __nv_bfloat16 g_A2hi[MPAD * DD];
__device__ __nv_bfloat16 g_A2lo[MPAD * DD];
__device__ __nv_bfloat16 g_Whi[2 * LL * DD * DD];
__device__ __nv_bfloat16 g_Wlo[2 * LL * DD * DD];
__device__ int   g_deg[NN];
__device__ int   g_off[NN + 1];
__device__ int   g_cur[NN];
__device__ int   g_pack[EE];     // (src << 3) | attr
__device__ float g_sumL[LL * 2 * DD];
__device__ float g_sqL[LL * 2 * DD];

// ---------------- PTX helpers ----------------
__device__ __forceinline__ uint32_t smem_u32(const void* p) {
    uint32_t a;
    asm("{ .reg .u64 t; cvta.to.shared.u64 t, %1; cvt.u32.u64 %0, t; }" : "=r"(a) : "l"(p));
    return a;
}
__device__ __forceinline__ void ldsm4(uint32_t* r, uint32_t addr) {
    asm volatile("ldmatrix.sync.aligned.m8n8.x4.shared.b16 {%0,%1,%2,%3}, [%4];"
                 : "=r"(r[0]), "=r"(r[1]), "=r"(r[2]), "=r"(r[3]) : "r"(addr));
}
__device__ __forceinline__ void mma16816(float* d, const uint32_t* a, const uint32_t* b) {
    asm volatile(
        "mma.sync.aligned.m16n8k16.row.col.f32.bf16.bf16.f32 "
        "{%0,%1,%2,%3}, {%4,%5,%6,%7}, {%8,%9}, {%0,%1,%2,%3};"
        : "+f"(d[0]), "+f"(d[1]), "+f"(d[2]), "+f"(d[3])
        : "r"(a[0]), "r"(a[1]), "r"(a[2]), "r"(a[3]), "r"(b[0]), "r"(b[1]));
}
__device__ __forceinline__ void cp16(uint32_t dst, const void* src) {
    asm volatile("cp.async.cg.shared.global [%0], [%1], 16;" :: "r"(dst), "l"(src));
}
__device__ __forceinline__ void cp_commit_wait() {
    asm volatile("cp.async.commit_group;" ::: "memory");
    asm volatile("cp.async.wait_group 0;" ::: "memory");
}

// ---------------- small vector helpers ----------------
__device__ __forceinline__ float4 f4relu(float4 a) {
    return make_float4(fmaxf(a.x, 0.f), fmaxf(a.y, 0.f), fmaxf(a.z, 0.f), fmaxf(a.w, 0.f));
}
__device__ __forceinline__ float4 f4s(float s, float4 a) {
    return make_float4(s * a.x, s * a.y, s * a.z, s * a.w);
}
__device__ __forceinline__ uint32_t packh2(float a, float b) {
    __half2 h = __floats2half2_rn(a, b);
    return *(uint32_t*)&h;
}
// bf16 hi/lo split of a float4
__device__ __forceinline__ void split4(float4 r, uint2* hi, uint2* lo) {
    __nv_bfloat16 hx = __float2bfloat16(r.x), hy = __float2bfloat16(r.y);
    __nv_bfloat16 hz = __float2bfloat16(r.z), hw = __float2bfloat16(r.w);
    __nv_bfloat16 lx = __float2bfloat16(r.x - __bfloat162float(hx));
    __nv_bfloat16 ly = __float2bfloat16(r.y - __bfloat162float(hy));
    __nv_bfloat16 lz = __float2bfloat16(r.z - __bfloat162float(hz));
    __nv_bfloat16 lw = __float2bfloat16(r.w - __bfloat162float(hw));
    hi->x = (uint32_t)__bfloat16_as_ushort(hx) | ((uint32_t)__bfloat16_as_ushort(hy) << 16);
    hi->y = (uint32_t)__bfloat16_as_ushort(hz) | ((uint32_t)__bfloat16_as_ushort(hw) << 16);
    lo->x = (uint32_t)__bfloat16_as_ushort(lx) | ((uint32_t)__bfloat16_as_ushort(ly) << 16);
    lo->y = (uint32_t)__bfloat16_as_ushort(lz) | ((uint32_t)__bfloat16_as_ushort(lw) << 16);
}

// ---------------- CSR build ----------------
__global__ void k_hist(const int* __restrict__ ei) {
    int e = blockIdx.x * blockDim.x + threadIdx.x;
    if (e < EE) atomicAdd(&g_deg[ei[EE + e]], 1);
}

__global__ void k_scan() {
    __shared__ int wsum[32];
    __shared__ int carry;
    int tid = threadIdx.x, lane = tid & 31, w = tid >> 5;
    if (tid == 0) { carry = 0; g_off[0] = 0; }
    __syncthreads();
    for (int base = 0; base < NN; base += 1024) {
        int i = base + tid;
        int v = (i < NN) ? g_deg[i] : 0;
        int x = v;
#pragma unroll
        for (int o = 1; o < 32; o <<= 1) {
            int y = __shfl_up_sync(0xffffffffu, x, o);
            if (lane >= o) x += y;
        }
        if (lane == 31) wsum[w] = x;
        __syncthreads();
        if (w == 0) {
            int s = wsum[lane];
#pragma unroll
            for (int o = 1; o < 32; o <<= 1) {
                int y = __shfl_up_sync(0xffffffffu, s, o);
                if (lane >= o) s += y;
            }
            wsum[lane] = s;
        }
        __syncthreads();
        int incl = x + (w ? wsum[w - 1] : 0) + carry;
        if (i < NN) { g_off[i + 1] = incl; g_cur[i] = incl - v; }
        __syncthreads();
        if (tid == 1023) carry = incl;
        __syncthreads();
    }
}

__global__ void k_scatter(const int* __restrict__ ei, const int* __restrict__ ea) {
    int e = blockIdx.x * blockDim.x + threadIdx.x;
    if (e < EE) {
        int d = ei[EE + e];
        int p = atomicAdd(&g_cur[d], 1);
        g_pack[p] = (ei[e] << 3) | ea[e];
    }
}

// ---------------- merged prologue: deg/stat zero + W bf16 split + encode -----
__global__ void k_prep(const float* __restrict__ Wfull, const int* __restrict__ x,
                       const float* __restrict__ ne1, const float* __restrict__ ne2) {
    int i = blockIdx.x * blockDim.x + threadIdx.x;
    if (i < NN) g_deg[i] = 0;
    if (i < LL * 2 * DD) { g_sumL[i] = 0.f; g_sqL[i] = 0.f; }
    if (i < 2 * LL * DD * DD) {
        float v = Wfull[i];
        __nv_bfloat16 h = __float2bfloat16(v);
        g_Whi[i] = h;
        g_Wlo[i] = __float2bfloat16(v - __bfloat162float(h));
    }
    if (i < NN * 32) {
        int n = i >> 5, c = i & 31;
        int xv = x[n];
        float4 a = ((const float4*)ne1)[xv * 32 + c];
        float4 b = ((const float4*)ne2)[xv * 32 + c];
        uint4 u;
        u.x = packh2(a.x, a.y); u.y = packh2(a.z, a.w);
        u.z = packh2(b.x, b.y); u.w = packh2(b.z, b.w);
        g_hh[n * 32 + c] = u;
    }
}

// ---------------- gather aggregation: one uint4 per edge-row per lane --------
__global__ __launch_bounds__(512) void k_aggregate(const float* __restrict__ eemb,
                                                   const float* __restrict__ eps_ptr,
                                                   int layer) {
    __shared__ float4 s_et[2 * EVV * 32];
    int tid = threadIdx.x;
    const float* et1 = eemb + (0 * LL + layer) * EVV * DD;
    const float* et2 = eemb + (1 * LL + layer) * EVV * DD;
    if (tid < 2 * EVV * 32) {
        if (tid < EVV * 32) s_et[tid] = ((const float4*)et1)[tid];
        else                s_et[tid] = ((const float4*)et2)[tid - EVV * 32];
    }
    __syncthreads();

    int warp = tid >> 5, lane = tid & 31;
    int n = blockIdx.x * 16 + warp;           // grid 1250 * 16 = 20000 exactly

    int beg = g_off[n], deg = g_off[n + 1] - beg;
    float4 acc1 = make_float4(0.f, 0.f, 0.f, 0.f);
    float4 acc2 = make_float4(0.f, 0.f, 0.f, 0.f);

    for (int base = 0; base < deg; base += 32) {
        int idx = base + lane;
        int pk = (idx < deg) ? __ldg(&g_pack[beg + idx]) : 0;
        int cnt = min(32, deg - base);
        int k = 0;
        for (; k + 4 <= cnt; k += 4) {
            int pa[4];
            uint4 u[4];
#pragma unroll
            for (int j = 0; j < 4; j++) pa[j] = __shfl_sync(0xffffffffu, pk, k + j);
#pragma unroll
            for (int j = 0; j < 4; j++)
                u[j] = __ldg(&g_hh[(pa[j] >> 3) * 32 + lane]);
#pragma unroll
            for (int j = 0; j < 4; j++) {
                int a = pa[j] & 7;
                float2 fa = __half22float2(*(__half2*)&u[j].x);
                float2 fb = __half22float2(*(__half2*)&u[j].y);
                float2 fc = __half22float2(*(__half2*)&u[j].z);
                float2 fd = __half22float2(*(__half2*)&u[j].w);
                float4 t1 = s_et[a * 32 + lane];
                float4 t2 = s_et[EVV * 32 + a * 32 + lane];
                acc1.x += fmaxf(fa.x + t1.x, 0.f);
                acc1.y += fmaxf(fa.y + t1.y, 0.f);
                acc1.z += fmaxf(fb.x + t1.z, 0.f);
                acc1.w += fmaxf(fb.y + t1.w, 0.f);
                acc2.x += fmaxf(fc.x + t2.x, 0.f);
                acc2.y += fmaxf(fc.y + t2.y, 0.f);
                acc2.z += fmaxf(fd.x + t2.z, 0.f);
                acc2.w += fmaxf(fd.y + t2.w, 0.f);
            }
        }
        for (; k < cnt; k++) {
            int p = __shfl_sync(0xffffffffu, pk, k);
            int a = p & 7;
            uint4 u = __ldg(&g_hh[(p >> 3) * 32 + lane]);
            float2 fa = __half22float2(*(__half2*)&u.x);
            float2 fb = __half22float2(*(__half2*)&u.y);
            float2 fc = __half22float2(*(__half2*)&u.z);
            float2 fd = __half22float2(*(__half2*)&u.w);
            float4 t1 = s_et[a * 32 + lane];
            float4 t2 = s_et[EVV * 32 + a * 32 + lane];
            acc1.x += fmaxf(fa.x + t1.x, 0.f);
            acc1.y += fmaxf(fa.y + t1.y, 0.f);
            acc1.z += fmaxf(fb.x + t1.z, 0.f);
            acc1.w += fmaxf(fb.y + t1.w, 0.f);
            acc2.x += fmaxf(fc.x + t2.x, 0.f);
            acc2.y += fmaxf(fc.y + t2.y, 0.f);
            acc2.z += fmaxf(fd.x + t2.z, 0.f);
            acc2.w += fmaxf(fd.y + t2.w, 0.f);
        }
    }
    float e1 = 1.f + eps_ptr[layer];
    float e2 = 1.f + eps_ptr[LL + layer];
    uint4 u = __ldg(&g_hh[n * 32 + lane]);
    float2 fa = __half22float2(*(__half2*)&u.x);
    float2 fb = __half22float2(*(__half2*)&u.y);
    float2 fc = __half22float2(*(__half2*)&u.z);
    float2 fd = __half22float2(*(__half2*)&u.w);
    float4 r1 = make_float4(fmaf(e1, fa.x, acc1.x), fmaf(e1, fa.y, acc1.y),
                            fmaf(e1, fb.x, acc1.z), fmaf(e1, fb.y, acc1.w));
    float4 r2 = make_float4(fmaf(e2, fc.x, acc2.x), fmaf(e2, fc.y, acc2.y),
                            fmaf(e2, fd.x, acc2.z), fmaf(e2, fd.y, acc2.w));

    uint2 hi, lo;
    split4(r1, &hi, &lo);
    *(uint2*)&g_A1hi[n * DD + lane * 4] = hi;
    *(uint2*)&g_A1lo[n * DD + lane * 4] = lo;
    split4(r2, &hi, &lo);
    *(uint2*)&g_A2hi[n * DD + lane * 4] = hi;
    *(uint2*)&g_A2lo[n * DD + lane * 4] = lo;
}

// ---------------- HMMA GEMM: Y = A @ W^T + b (bf16 hi/lo x3, fp32 acc) -------
// BM=64 -> SMEM 96KB: Ahi 16K | Alo 16K | Whi 32K | Wlo 32K  (2 blocks/SM)
#define SA_HI 0
#define SA_LO 16384
#define SW_HI 32768
#define SW_LO 65536
#define SM_GEMM_TOTAL 98304

__global__ __launch_bounds__(256, 2) void k_gemm_tc(const float* __restrict__ bfull,
                                                    int layer) {
    extern __shared__ char smem[];
    uint32_t sbase = smem_u32(smem);
    int tid = threadIdx.x;
    int wid = tid >> 5, lane = tid & 31;

    int t = blockIdx.y;
    const __nv_bfloat16* Ahi = t ? g_A2hi : g_A1hi;
    const __nv_bfloat16* Alo = t ? g_A2lo : g_A1lo;
    const __nv_bfloat16* Whi = g_Whi + (t * LL + layer) * DD * DD;
    const __nv_bfloat16* Wlo = g_Wlo + (t * LL + layer) * DD * DD;
    float* Y = t ? g_Y2 : g_Y1;
    const float* bp = bfull + (t * LL + layer) * DD;
    int m0 = blockIdx.x * 64;

    // A tiles: 2 x 1024 chunks of 16B
    for (int i = tid; i < 2048; i += 256) {
        int half = i >> 10;
        int idx = i & 1023;
        int row = idx >> 4, ch = idx & 15;
        uint32_t so = (uint32_t)row * 256u + (uint32_t)((ch ^ (row & 7)) << 4);
        const __nv_bfloat16* src = (half ? Alo : Ahi) + (size_t)(m0 + row) * DD;
        cp16(sbase + (half ? SA_LO : SA_HI) + so, (const char*)src + ch * 16);
    }
    // W tiles: 2 x 2048 chunks
    for (int i = tid; i < 4096; i += 256) {
        int half = i >> 11;
        int idx = i & 2047;
        int row = idx >> 4, ch = idx & 15;
        uint32_t so = (uint32_t)row * 256u + (uint32_t)((ch ^ (row & 7)) << 4);
        const __nv_bfloat16* src = (half ? Wlo : Whi) + (size_t)row * DD;
        cp16(sbase + (half ? SW_LO : SW_HI) + so, (const char*)src + ch * 16);
    }
    cp_commit_wait();
    __syncthreads();

    // warp tiling: 2 (m) x 4 (n); warp tile 32x32
    int wm = wid & 1, wn = wid >> 1;
    int grp = lane >> 3, r8 = lane & 7;
    int a_row0 = wm * 32 + (grp & 1) * 8 + r8;
    int b_row0 = wn * 32 + (grp >> 1) * 8 + r8;
    int kselA = grp >> 1;
    int kselB = grp & 1;

    float acc[2][4][4];
#pragma unroll
    for (int i = 0; i < 2; i++)
#pragma unroll
        for (int j = 0; j < 4; j++)
#pragma unroll
            for (int q = 0; q < 4; q++) acc[i][j][q] = 0.f;

#pragma unroll
    for (int p = 0; p < 3; p++) {
        uint32_t Ab = sbase + ((p == 2) ? SA_LO : SA_HI);
        uint32_t Bb = sbase + ((p == 1) ? SW_LO : SW_HI);
#pragma unroll
        for (int ks = 0; ks < 8; ks++) {
            uint32_t af[2][4], bf[2][4];
            uint32_t aoff = (uint32_t)(((ks * 2 + kselA) ^ r8) << 4);
            ldsm4(af[0], Ab + (uint32_t)a_row0 * 256u + aoff);
            ldsm4(af[1], Ab + (uint32_t)(a_row0 + 16) * 256u + aoff);
            uint32_t boff = (uint32_t)(((ks * 2 + kselB) ^ r8) << 4);
            ldsm4(bf[0], Bb + (uint32_t)b_row0 * 256u + boff);
            ldsm4(bf[1], Bb + (uint32_t)(b_row0 + 16) * 256u + boff);
#pragma unroll
            for (int i = 0; i < 2; i++)
#pragma unroll
                for (int j = 0; j < 4; j++)
                    mma16816(acc[i][j], af[i], &bf[j >> 1][(j & 1) * 2]);
        }
    }

    float* gsum = g_sumL + layer * 2 * DD + t * DD;
    float* gsq = g_sqL + layer * 2 * DD + t * DD;
    int qr = lane >> 2, qc = lane & 3;
#pragma unroll
    for (int j = 0; j < 4; j++) {
        int c0 = wn * 32 + j * 8 + qc * 2;
        float bb0 = bp[c0], bb1 = bp[c0 + 1];
        float s0 = 0.f, s1 = 0.f, q0 = 0.f, q1 = 0.f;
#pragma unroll
        for (int i = 0; i < 2; i++) {
#pragma unroll
            for (int h = 0; h < 2; h++) {
                int m = m0 + wm * 32 + i * 16 + qr + h * 8;
                float v0 = acc[i][j][h * 2 + 0] + bb0;
                float v1 = acc[i][j][h * 2 + 1] + bb1;
                if (m < NN) {
                    *(float2*)&Y[m * DD + c0] = make_float2(v0, v1);
                    s0 += v0; s1 += v1;
                    q0 += v0 * v0; q1 += v1 * v1;
                }
            }
        }
#pragma unroll
        for (int off = 4; off < 32; off <<= 1) {
            s0 += __shfl_xor_sync(0xffffffffu, s0, off);
            s1 += __shfl_xor_sync(0xffffffffu, s1, off);
            q0 += __shfl_xor_sync(0xffffffffu, q0, off);
            q1 += __shfl_xor_sync(0xffffffffu, q1, off);
        }
        if (qr == 0) {
            atomicAdd(&gsum[c0], s0);
            atomicAdd(&gsum[c0 + 1], s1);
            atomicAdd(&gsq[c0], q0);
            atomicAdd(&gsq[c0 + 1], q1);
        }
    }
}

// ---------------- BN + relu + cross-stitch (per node) ----------------
__global__ void k_bn_cross(const float* __restrict__ gam,
                           const float* __restrict__ bet,
                           const float* __restrict__ cu,
                           int layer, int last, float* __restrict__ out) {
    int idx = blockIdx.x * blockDim.x + threadIdx.x;
    if (idx >= NN * 32) return;
    int n = idx >> 5, c4 = idx & 31;
    int f = c4 * 4;
    const float inv = 1.f / (float)NN;
    const float* gsum = g_sumL + layer * 2 * DD;
    const float* gsq = g_sqL + layer * 2 * DD;

    float4 s1 = *(const float4*)&gsum[f];
    float4 q1 = *(const float4*)&gsq[f];
    float4 s2 = *(const float4*)&gsum[DD + f];
    float4 q2 = *(const float4*)&gsq[DD + f];

    float4 mu1 = f4s(inv, s1), mu2 = f4s(inv, s2);
    float4 rs1 = make_float4(rsqrtf(q1.x * inv - mu1.x * mu1.x + BN_EPS),
                             rsqrtf(q1.y * inv - mu1.y * mu1.y + BN_EPS),
                             rsqrtf(q1.z * inv - mu1.z * mu1.z + BN_EPS),
                             rsqrtf(q1.w * inv - mu1.w * mu1.w + BN_EPS));
    float4 rs2 = make_float4(rsqrtf(q2.x * inv - mu2.x * mu2.x + BN_EPS),
                             rsqrtf(q2.y * inv - mu2.y * mu2.y + BN_EPS),
                             rsqrtf(q2.z * inv - mu2.z * mu2.z + BN_EPS),
                             rsqrtf(q2.w * inv - mu2.w * mu2.w + BN_EPS));

    float4 g1 = *(const float4*)&gam[(0 * LL + layer) * DD + f];
    float4 b1 = *(const float4*)&bet[(0 * LL + layer) * DD + f];
    float4 g2 = *(const float4*)&gam[(1 * LL + layer) * DD + f];
    float4 b2 = *(const float4*)&bet[(1 * LL + layer) * DD + f];

    float4 y1 = ((const float4*)g_Y1)[n * 32 + c4];
    float4 y2 = ((const float4*)g_Y2)[n * 32 + c4];

    y1.x = (y1.x - mu1.x) * rs1.x * g1.x + b1.x;
    y1.y = (y1.y - mu1.y) * rs1.y * g1.y + b1.y;
    y1.z = (y1.z - mu1.z) * rs1.z * g1.z + b1.z;
    y1.w = (y1.w - mu1.w) * rs1.w * g1.w + b1.w;
    y2.x = (y2.x - mu2.x) * rs2.x * g2.x + b2.x;
    y2.y = (y2.y - mu2.y) * rs2.y * g2.y + b2.y;
    y2.z = (y2.z - mu2.z) * rs2.z * g2.z + b2.z;
    y2.w = (y2.w - mu2.w) * rs2.w * g2.w + b2.w;

    if (!last) {
        y1 = f4relu(y1);
        y2 = f4relu(y2);
    }

    float c00 = cu[layer * 4 + 0], c01 = cu[layer * 4 + 1];
    float c10 = cu[layer * 4 + 2], c11 = cu[layer * 4 + 3];

    float4 n1 = make_float4(c00 * y1.x + c01 * y2.x, c00 * y1.y + c01 * y2.y,
                            c00 * y1.z + c01 * y2.z, c00 * y1.w + c01 * y2.w);
    float4 n2 = make_float4(c10 * n1.x + c11 * y2.x, c10 * n1.y + c11 * y2.y,
                            c10 * n1.z + c11 * y2.z, c10 * n1.w + c11 * y2.w);

    if (last) {
        ((float4*)out)[n * 32 + c4] = n1;
        ((float4*)out)[NN * 32 + n * 32 + c4] = n2;
    } else {
        uint4 u;
        u.x = packh2(n1.x, n1.y); u.y = packh2(n1.z, n1.w);
        u.z = packh2(n2.x, n2.y); u.w = packh2(n2.z, n2.w);
        g_hh[n * 32 + c4] = u;
    }
}

// ---------------- launch ----------------
extern "C" void kernel_launch(void* const* d_in, const int* in_sizes, int n_in,
                              void* d_out, int out_size) {
    const int* x = (const int*)d_in[0];
    const int* ei = (const int*)d_in[1];
    const int* ea = (const int*)d_in[2];
    const float* ne1 = (const float*)d_in[3];
    const float* ne2 = (const float*)d_in[4];
    const float* eemb = (const float*)d_in[5];
    const float* eps = (const float*)d_in[6];
    const float* W = (const float*)d_in[7];
    const float* b = (const float*)d_in[8];
    const float* gam = (const float*)d_in[9];
    const float* bet = (const float*)d_in[10];
    const float* cu = (const float*)d_in[11];
    float* out = (float*)d_out;

    static int smem_set = 0;
    if (!smem_set) {
        cudaFuncSetAttribute(k_gemm_tc, cudaFuncAttributeMaxDynamicSharedMemorySize,
                             SM_GEMM_TOTAL);
        smem_set = 1;
    }

    k_prep<<<(NN * 32 + 255) / 256, 256>>>(W, x, ne1, ne2);
    k_hist<<<(EE + 255) / 256, 256>>>(ei);
    k_scan<<<1, 1024>>>();
    k_scatter<<<(EE + 255) / 256, 256>>>(ei, ea);

    for (int l = 0; l < LL; l++) {
        k_aggregate<<<NN / 16, 512>>>(eemb, eps, l);
        dim3 gg((NN + 63) / 64, 2);
        k_gemm_tc<<<gg, 256, SM_GEMM_TOTAL>>>(b, l);
        k_bn_cross<<<(NN * 32 + 255) / 256, 256>>>(gam, bet, cu, l, (l == LL - 1) ? 1 : 0, out);
    }
}

// round 14
// speedup vs baseline: 1.4980x; 1.0329x over previous
#include <cuda_runtime.h>
#include <cuda_bf16.h>
#include <cuda_fp16.h>
#include <cstdint>

#define NN 20000
#define EE 320000
#define DD 128
#define LL 5
#define EVV 5
#define BN_EPS 1e-5f
#define MPAD 20096

// ---------------- device scratch (no allocation allowed) ----------------
__device__ uint4 g_hh[NN * 32];        // fp16 h, [node][fg]: {t1 f0..3, t2 f0..3}
__device__ float g_Y1[NN * DD];
__device__ float g_Y2[NN * DD];
__device__ __nv_bfloat16 g_A1hi[MPAD * DD];
__device__ __nv_bfloat16 g_A1lo[MPAD * DD];
__device__ __nv_bfloat16 g_A2hi[MPAD * DD];
__device__ __nv_bfloat16 g_A2lo[MPAD * DD];
__device__ __nv_bfloat16 g_Whi[2 * LL * DD * DD];
__device__ __nv_bfloat16 g_Wlo[2 * LL * DD * DD];
__device__ int   g_deg[NN];
__device__ int   g_off[NN + 1];
__device__ int   g_cur[NN];
__device__ int   g_pack[EE];     // (src << 3) | attr
__device__ float g_sumL[LL * 2 * DD];
__device__ float g_sqL[LL * 2 * DD];

// ---------------- PTX helpers ----------------
__device__ __forceinline__ uint32_t smem_u32(const void* p) {
    uint32_t a;
    asm("{ .reg .u64 t; cvta.to.shared.u64 t, %1; cvt.u32.u64 %0, t; }" : "=r"(a) : "l"(p));
    return a;
}
__device__ __forceinline__ void ldsm4(uint32_t* r, uint32_t addr) {
    asm volatile("ldmatrix.sync.aligned.m8n8.x4.shared.b16 {%0,%1,%2,%3}, [%4];"
                 : "=r"(r[0]), "=r"(r[1]), "=r"(r[2]), "=r"(r[3]) : "r"(addr));
}
__device__ __forceinline__ void mma16816(float* d, const uint32_t* a, const uint32_t* b) {
    asm volatile(
        "mma.sync.aligned.m16n8k16.row.col.f32.bf16.bf16.f32 "
        "{%0,%1,%2,%3}, {%4,%5,%6,%7}, {%8,%9}, {%0,%1,%2,%3};"
        : "+f"(d[0]), "+f"(d[1]), "+f"(d[2]), "+f"(d[3])
        : "r"(a[0]), "r"(a[1]), "r"(a[2]), "r"(a[3]), "r"(b[0]), "r"(b[1]));
}
__device__ __forceinline__ void cp16(uint32_t dst, const void* src) {
    asm volatile("cp.async.cg.shared.global [%0], [%1], 16;" :: "r"(dst), "l"(src));
}
__device__ __forceinline__ void cp_commit_wait() {
    asm volatile("cp.async.commit_group;" ::: "memory");
    asm volatile("cp.async.wait_group 0;" ::: "memory");
}

// ---------------- small vector helpers ----------------
__device__ __forceinline__ float4 f4relu(float4 a) {
    return make_float4(fmaxf(a.x, 0.f), fmaxf(a.y, 0.f), fmaxf(a.z, 0.f), fmaxf(a.w, 0.f));
}
__device__ __forceinline__ float4 f4s(float s, float4 a) {
    return make_float4(s * a.x, s * a.y, s * a.z, s * a.w);
}
__device__ __forceinline__ uint32_t packh2(float a, float b) {
    __half2 h = __floats2half2_rn(a, b);
    return *(uint32_t*)&h;
}
__device__ __forceinline__ __half2 u2h2(uint32_t u) { return *(__half2*)&u; }
// bf16 hi/lo split of a float4
__device__ __forceinline__ void split4(float4 r, uint2* hi, uint2* lo) {
    __nv_bfloat16 hx = __float2bfloat16(r.x), hy = __float2bfloat16(r.y);
    __nv_bfloat16 hz = __float2bfloat16(r.z), hw = __float2bfloat16(r.w);
    __nv_bfloat16 lx = __float2bfloat16(r.x - __bfloat162float(hx));
    __nv_bfloat16 ly = __float2bfloat16(r.y - __bfloat162float(hy));
    __nv_bfloat16 lz = __float2bfloat16(r.z - __bfloat162float(hz));
    __nv_bfloat16 lw = __float2bfloat16(r.w - __bfloat162float(hw));
    hi->x = (uint32_t)__bfloat16_as_ushort(hx) | ((uint32_t)__bfloat16_as_ushort(hy) << 16);
    hi->y = (uint32_t)__bfloat16_as_ushort(hz) | ((uint32_t)__bfloat16_as_ushort(hw) << 16);
    lo->x = (uint32_t)__bfloat16_as_ushort(lx) | ((uint32_t)__bfloat16_as_ushort(ly) << 16);
    lo->y = (uint32_t)__bfloat16_as_ushort(lz) | ((uint32_t)__bfloat16_as_ushort(lw) << 16);
}

// ---------------- CSR build ----------------
__global__ void k_hist(const int* __restrict__ ei) {
    int e = blockIdx.x * blockDim.x + threadIdx.x;
    if (e < EE) atomicAdd(&g_deg[ei[EE + e]], 1);
}

__global__ void k_scan() {
    __shared__ int wsum[32];
    __shared__ int carry;
    int tid = threadIdx.x, lane = tid & 31, w = tid >> 5;
    if (tid == 0) { carry = 0; g_off[0] = 0; }
    __syncthreads();
    for (int base = 0; base < NN; base += 1024) {
        int i = base + tid;
        int v = (i < NN) ? g_deg[i] : 0;
        int x = v;
#pragma unroll
        for (int o = 1; o < 32; o <<= 1) {
            int y = __shfl_up_sync(0xffffffffu, x, o);
            if (lane >= o) x += y;
        }
        if (lane == 31) wsum[w] = x;
        __syncthreads();
        if (w == 0) {
            int s = wsum[lane];
#pragma unroll
            for (int o = 1; o < 32; o <<= 1) {
                int y = __shfl_up_sync(0xffffffffu, s, o);
                if (lane >= o) s += y;
            }
            wsum[lane] = s;
        }
        __syncthreads();
        int incl = x + (w ? wsum[w - 1] : 0) + carry;
        if (i < NN) { g_off[i + 1] = incl; g_cur[i] = incl - v; }
        __syncthreads();
        if (tid == 1023) carry = incl;
        __syncthreads();
    }
}

__global__ void k_scatter(const int* __restrict__ ei, const int* __restrict__ ea) {
    int e = blockIdx.x * blockDim.x + threadIdx.x;
    if (e < EE) {
        int d = ei[EE + e];
        int p = atomicAdd(&g_cur[d], 1);
        g_pack[p] = (ei[e] << 3) | ea[e];
    }
}

// ---------------- merged prologue: deg/stat zero + W bf16 split + encode -----
__global__ void k_prep(const float* __restrict__ Wfull, const int* __restrict__ x,
                       const float* __restrict__ ne1, const float* __restrict__ ne2) {
    int i = blockIdx.x * blockDim.x + threadIdx.x;
    if (i < NN) g_deg[i] = 0;
    if (i < LL * 2 * DD) { g_sumL[i] = 0.f; g_sqL[i] = 0.f; }
    if (i < 2 * LL * DD * DD) {
        float v = Wfull[i];
        __nv_bfloat16 h = __float2bfloat16(v);
        g_Whi[i] = h;
        g_Wlo[i] = __float2bfloat16(v - __bfloat162float(h));
    }
    if (i < NN * 32) {
        int n = i >> 5, c = i & 31;
        int xv = x[n];
        float4 a = ((const float4*)ne1)[xv * 32 + c];
        float4 b = ((const float4*)ne2)[xv * 32 + c];
        uint4 u;
        u.x = packh2(a.x, a.y); u.y = packh2(a.z, a.w);
        u.z = packh2(b.x, b.y); u.w = packh2(b.z, b.w);
        g_hh[n * 32 + c] = u;
    }
}

// ---------------- gather aggregation: half2 message math, fp32 accumulate ----
__global__ __launch_bounds__(512, 2) void k_aggregate(const float* __restrict__ eemb,
                                                      const float* __restrict__ eps_ptr,
                                                      int layer) {
    __shared__ uint4 s_eth[EVV * 32];   // fp16 edge tables, interleaved like g_hh
    int tid = threadIdx.x;
    const float* et1 = eemb + (0 * LL + layer) * EVV * DD;
    const float* et2 = eemb + (1 * LL + layer) * EVV * DD;
    if (tid < EVV * 32) {
        float4 t1 = ((const float4*)et1)[tid];
        float4 t2 = ((const float4*)et2)[tid];
        uint4 u;
        u.x = packh2(t1.x, t1.y); u.y = packh2(t1.z, t1.w);
        u.z = packh2(t2.x, t2.y); u.w = packh2(t2.z, t2.w);
        s_eth[tid] = u;
    }
    __syncthreads();

    int warp = tid >> 5, lane = tid & 31;
    int n = blockIdx.x * 16 + warp;           // grid 1250 * 16 = 20000 exactly

    int beg = g_off[n], deg = g_off[n + 1] - beg;
    float4 acc1 = make_float4(0.f, 0.f, 0.f, 0.f);
    float4 acc2 = make_float4(0.f, 0.f, 0.f, 0.f);
    const __half2 zero2 = __floats2half2_rn(0.f, 0.f);

    for (int base = 0; base < deg; base += 32) {
        int idx = base + lane;
        int pk = (idx < deg) ? __ldg(&g_pack[beg + idx]) : 0;
        int cnt = min(32, deg - base);
        int k = 0;
        for (; k + 4 <= cnt; k += 4) {
            int pa[4];
            uint4 u[4];
#pragma unroll
            for (int j = 0; j < 4; j++) pa[j] = __shfl_sync(0xffffffffu, pk, k + j);
#pragma unroll
            for (int j = 0; j < 4; j++)
                u[j] = __ldg(&g_hh[(pa[j] >> 3) * 32 + lane]);
#pragma unroll
            for (int j = 0; j < 4; j++) {
                uint4 t = s_eth[(pa[j] & 7) * 32 + lane];
                __half2 m0 = __hmax2(__hadd2(u2h2(u[j].x), u2h2(t.x)), zero2);
                __half2 m1 = __hmax2(__hadd2(u2h2(u[j].y), u2h2(t.y)), zero2);
                __half2 m2 = __hmax2(__hadd2(u2h2(u[j].z), u2h2(t.z)), zero2);
                __half2 m3 = __hmax2(__hadd2(u2h2(u[j].w), u2h2(t.w)), zero2);
                float2 f0 = __half22float2(m0);
                float2 f1 = __half22float2(m1);
                float2 f2 = __half22float2(m2);
                float2 f3 = __half22float2(m3);
                acc1.x += f0.x; acc1.y += f0.y; acc1.z += f1.x; acc1.w += f1.y;
                acc2.x += f2.x; acc2.y += f2.y; acc2.z += f3.x; acc2.w += f3.y;
            }
        }
        for (; k < cnt; k++) {
            int p = __shfl_sync(0xffffffffu, pk, k);
            uint4 u = __ldg(&g_hh[(p >> 3) * 32 + lane]);
            uint4 t = s_eth[(p & 7) * 32 + lane];
            __half2 m0 = __hmax2(__hadd2(u2h2(u.x), u2h2(t.x)), zero2);
            __half2 m1 = __hmax2(__hadd2(u2h2(u.y), u2h2(t.y)), zero2);
            __half2 m2 = __hmax2(__hadd2(u2h2(u.z), u2h2(t.z)), zero2);
            __half2 m3 = __hmax2(__hadd2(u2h2(u.w), u2h2(t.w)), zero2);
            float2 f0 = __half22float2(m0);
            float2 f1 = __half22float2(m1);
            float2 f2 = __half22float2(m2);
            float2 f3 = __half22float2(m3);
            acc1.x += f0.x; acc1.y += f0.y; acc1.z += f1.x; acc1.w += f1.y;
            acc2.x += f2.x; acc2.y += f2.y; acc2.z += f3.x; acc2.w += f3.y;
        }
    }
    float e1 = 1.f + eps_ptr[layer];
    float e2 = 1.f + eps_ptr[LL + layer];
    uint4 u = __ldg(&g_hh[n * 32 + lane]);
    float2 fa = __half22float2(u2h2(u.x));
    float2 fb = __half22float2(u2h2(u.y));
    float2 fc = __half22float2(u2h2(u.z));
    float2 fd = __half22float2(u2h2(u.w));
    float4 r1 = make_float4(fmaf(e1, fa.x, acc1.x), fmaf(e1, fa.y, acc1.y),
                            fmaf(e1, fb.x, acc1.z), fmaf(e1, fb.y, acc1.w));
    float4 r2 = make_float4(fmaf(e2, fc.x, acc2.x), fmaf(e2, fc.y, acc2.y),
                            fmaf(e2, fd.x, acc2.z), fmaf(e2, fd.y, acc2.w));

    uint2 hi, lo;
    split4(r1, &hi, &lo);
    *(uint2*)&g_A1hi[n * DD + lane * 4] = hi;
    *(uint2*)&g_A1lo[n * DD + lane * 4] = lo;
    split4(r2, &hi, &lo);
    *(uint2*)&g_A2hi[n * DD + lane * 4] = hi;
    *(uint2*)&g_A2lo[n * DD + lane * 4] = lo;
}

// ---------------- HMMA GEMM: Y = A @ W^T + b (bf16 hi/lo x3, fp32 acc) -------
// BM=64 -> SMEM 96KB: Ahi 16K | Alo 16K | Whi 32K | Wlo 32K  (2 blocks/SM)
#define SA_HI 0
#define SA_LO 16384
#define SW_HI 32768
#define SW_LO 65536
#define SM_GEMM_TOTAL 98304

__global__ __launch_bounds__(256, 2) void k_gemm_tc(const float* __restrict__ bfull,
                                                    int layer) {
    extern __shared__ char smem[];
    uint32_t sbase = smem_u32(smem);
    int tid = threadIdx.x;
    int wid = tid >> 5, lane = tid & 31;

    int t = blockIdx.y;
    const __nv_bfloat16* Ahi = t ? g_A2hi : g_A1hi;
    const __nv_bfloat16* Alo = t ? g_A2lo : g_A1lo;
    const __nv_bfloat16* Whi = g_Whi + (t * LL + layer) * DD * DD;
    const __nv_bfloat16* Wlo = g_Wlo + (t * LL + layer) * DD * DD;
    float* Y = t ? g_Y2 : g_Y1;
    const float* bp = bfull + (t * LL + layer) * DD;
    int m0 = blockIdx.x * 64;

    for (int i = tid; i < 2048; i += 256) {
        int half = i >> 10;
        int idx = i & 1023;
        int row = idx >> 4, ch = idx & 15;
        uint32_t so = (uint32_t)row * 256u + (uint32_t)((ch ^ (row & 7)) << 4);
        const __nv_bfloat16* src = (half ? Alo : Ahi) + (size_t)(m0 + row) * DD;
        cp16(sbase + (half ? SA_LO : SA_HI) + so, (const char*)src + ch * 16);
    }
    for (int i = tid; i < 4096; i += 256) {
        int half = i >> 11;
        int idx = i & 2047;
        int row = idx >> 4, ch = idx & 15;
        uint32_t so = (uint32_t)row * 256u + (uint32_t)((ch ^ (row & 7)) << 4);
        const __nv_bfloat16* src = (half ? Wlo : Whi) + (size_t)row * DD;
        cp16(sbase + (half ? SW_LO : SW_HI) + so, (const char*)src + ch * 16);
    }
    cp_commit_wait();
    __syncthreads();

    int wm = wid & 1, wn = wid >> 1;
    int grp = lane >> 3, r8 = lane & 7;
    int a_row0 = wm * 32 + (grp & 1) * 8 + r8;
    int b_row0 = wn * 32 + (grp >> 1) * 8 + r8;
    int kselA = grp >> 1;
    int kselB = grp & 1;

    float acc[2][4][4];
#pragma unroll
    for (int i = 0; i < 2; i++)
#pragma unroll
        for (int j = 0; j < 4; j++)
#pragma unroll
            for (int q = 0; q < 4; q++) acc[i][j][q] = 0.f;

#pragma unroll
    for (int p = 0; p < 3; p++) {
        uint32_t Ab = sbase + ((p == 2) ? SA_LO : SA_HI);
        uint32_t Bb = sbase + ((p == 1) ? SW_LO : SW_HI);
#pragma unroll
        for (int ks = 0; ks < 8; ks++) {
            uint32_t af[2][4], bf[2][4];
            uint32_t aoff = (uint32_t)(((ks * 2 + kselA) ^ r8) << 4);
            ldsm4(af[0], Ab + (uint32_t)a_row0 * 256u + aoff);
            ldsm4(af[1], Ab + (uint32_t)(a_row0 + 16) * 256u + aoff);
            uint32_t boff = (uint32_t)(((ks * 2 + kselB) ^ r8) << 4);
            ldsm4(bf[0], Bb + (uint32_t)b_row0 * 256u + boff);
            ldsm4(bf[1], Bb + (uint32_t)(b_row0 + 16) * 256u + boff);
#pragma unroll
            for (int i = 0; i < 2; i++)
#pragma unroll
                for (int j = 0; j < 4; j++)
                    mma16816(acc[i][j], af[i], &bf[j >> 1][(j & 1) * 2]);
        }
    }

    float* gsum = g_sumL + layer * 2 * DD + t * DD;
    float* gsq = g_sqL + layer * 2 * DD + t * DD;
    int qr = lane >> 2, qc = lane & 3;
#pragma unroll
    for (int j = 0; j < 4; j++) {
        int c0 = wn * 32 + j * 8 + qc * 2;
        float bb0 = bp[c0], bb1 = bp[c0 + 1];
        float s0 = 0.f, s1 = 0.f, q0 = 0.f, q1 = 0.f;
#pragma unroll
        for (int i = 0; i < 2; i++) {
#pragma unroll
            for (int h = 0; h < 2; h++) {
                int m = m0 + wm * 32 + i * 16 + qr + h * 8;
                float v0 = acc[i][j][h * 2 + 0] + bb0;
                float v1 = acc[i][j][h * 2 + 1] + bb1;
                if (m < NN) {
                    *(float2*)&Y[m * DD + c0] = make_float2(v0, v1);
                    s0 += v0; s1 += v1;
                    q0 += v0 * v0; q1 += v1 * v1;
                }
            }
        }
#pragma unroll
        for (int off = 4; off < 32; off <<= 1) {
            s0 += __shfl_xor_sync(0xffffffffu, s0, off);
            s1 += __shfl_xor_sync(0xffffffffu, s1, off);
            q0 += __shfl_xor_sync(0xffffffffu, q0, off);
            q1 += __shfl_xor_sync(0xffffffffu, q1, off);
        }
        if (qr == 0) {
            atomicAdd(&gsum[c0], s0);
            atomicAdd(&gsum[c0 + 1], s1);
            atomicAdd(&gsq[c0], q0);
            atomicAdd(&gsq[c0 + 1], q1);
        }
    }
}

// ---------------- BN + relu + cross-stitch (per node) ----------------
__global__ void k_bn_cross(const float* __restrict__ gam,
                           const float* __restrict__ bet,
                           const float* __restrict__ cu,
                           int layer, int last, float* __restrict__ out) {
    int idx = blockIdx.x * blockDim.x + threadIdx.x;
    if (idx >= NN * 32) return;
    int n = idx >> 5, c4 = idx & 31;
    int f = c4 * 4;
    const float inv = 1.f / (float)NN;
    const float* gsum = g_sumL + layer * 2 * DD;
    const float* gsq = g_sqL + layer * 2 * DD;

    float4 s1 = *(const float4*)&gsum[f];
    float4 q1 = *(const float4*)&gsq[f];
    float4 s2 = *(const float4*)&gsum[DD + f];
    float4 q2 = *(const float4*)&gsq[DD + f];

    float4 mu1 = f4s(inv, s1), mu2 = f4s(inv, s2);
    float4 rs1 = make_float4(rsqrtf(q1.x * inv - mu1.x * mu1.x + BN_EPS),
                             rsqrtf(q1.y * inv - mu1.y * mu1.y + BN_EPS),
                             rsqrtf(q1.z * inv - mu1.z * mu1.z + BN_EPS),
                             rsqrtf(q1.w * inv - mu1.w * mu1.w + BN_EPS));
    float4 rs2 = make_float4(rsqrtf(q2.x * inv - mu2.x * mu2.x + BN_EPS),
                             rsqrtf(q2.y * inv - mu2.y * mu2.y + BN_EPS),
                             rsqrtf(q2.z * inv - mu2.z * mu2.z + BN_EPS),
                             rsqrtf(q2.w * inv - mu2.w * mu2.w + BN_EPS));

    float4 g1 = *(const float4*)&gam[(0 * LL + layer) * DD + f];
    float4 b1 = *(const float4*)&bet[(0 * LL + layer) * DD + f];
    float4 g2 = *(const float4*)&gam[(1 * LL + layer) * DD + f];
    float4 b2 = *(const float4*)&bet[(1 * LL + layer) * DD + f];

    float4 y1 = ((const float4*)g_Y1)[n * 32 + c4];
    float4 y2 = ((const float4*)g_Y2)[n * 32 + c4];

    y1.x = (y1.x - mu1.x) * rs1.x * g1.x + b1.x;
    y1.y = (y1.y - mu1.y) * rs1.y * g1.y + b1.y;
    y1.z = (y1.z - mu1.z) * rs1.z * g1.z + b1.z;
    y1.w = (y1.w - mu1.w) * rs1.w * g1.w + b1.w;
    y2.x = (y2.x - mu2.x) * rs2.x * g2.x + b2.x;
    y2.y = (y2.y - mu2.y) * rs2.y * g2.y + b2.y;
    y2.z = (y2.z - mu2.z) * rs2.z * g2.z + b2.z;
    y2.w = (y2.w - mu2.w) * rs2.w * g2.w + b2.w;

    if (!last) {
        y1 = f4relu(y1);
        y2 = f4relu(y2);
    }

    float c00 = cu[layer * 4 + 0], c01 = cu[layer * 4 + 1];
    float c10 = cu[layer * 4 + 2], c11 = cu[layer * 4 + 3];

    float4 n1 = make_float4(c00 * y1.x + c01 * y2.x, c00 * y1.y + c01 * y2.y,
                            c00 * y1.z + c01 * y2.z, c00 * y1.w + c01 * y2.w);
    float4 n2 = make_float4(c10 * n1.x + c11 * y2.x, c10 * n1.y + c11 * y2.y,
                            c10 * n1.z + c11 * y2.z, c10 * n1.w + c11 * y2.w);

    if (last) {
        ((float4*)out)[n * 32 + c4] = n1;
        ((float4*)out)[NN * 32 + n * 32 + c4] = n2;
    } else {
        uint4 u;
        u.x = packh2(n1.x, n1.y); u.y = packh2(n1.z, n1.w);
        u.z = packh2(n2.x, n2.y); u.w = packh2(n2.z, n2.w);
        g_hh[n * 32 + c4] = u;
    }
}

// ---------------- launch ----------------
extern "C" void kernel_launch(void* const* d_in, const int* in_sizes, int n_in,
                              void* d_out, int out_size) {
    const int* x = (const int*)d_in[0];
    const int* ei = (const int*)d_in[1];
    const int* ea = (const int*)d_in[2];
    const float* ne1 = (const float*)d_in[3];
    const float* ne2 = (const float*)d_in[4];
    const float* eemb = (const float*)d_in[5];
    const float* eps = (const float*)d_in[6];
    const float* W = (const float*)d_in[7];
    const float* b = (const float*)d_in[8];
    const float* gam = (const float*)d_in[9];
    const float* bet = (const float*)d_in[10];
    const float* cu = (const float*)d_in[11];
    float* out = (float*)d_out;

    static int smem_set = 0;
    if (!smem_set) {
        cudaFuncSetAttribute(k_gemm_tc, cudaFuncAttributeMaxDynamicSharedMemorySize,
                             SM_GEMM_TOTAL);
        smem_set = 1;
    }

    k_prep<<<(NN * 32 + 255) / 256, 256>>>(W, x, ne1, ne2);
    k_hist<<<(EE + 255) / 256, 256>>>(ei);
    k_scan<<<1, 1024>>>();
    k_scatter<<<(EE + 255) / 256, 256>>>(ei, ea);

    for (int l = 0; l < LL; l++) {
        k_aggregate<<<NN / 16, 512>>>(eemb, eps, l);
        dim3 gg((NN + 63) / 64, 2);
        k_gemm_tc<<<gg, 256, SM_GEMM_TOTAL>>>(b, l);
        k_bn_cross<<<(NN * 32 + 255) / 256, 256>>>(gam, bet, cu, l, (l == LL - 1) ? 1 : 0, out);
    }
}

// round 15
// speedup vs baseline: 1.5352x; 1.0248x over previous
#include <cuda_runtime.h>
#include <cuda_bf16.h>
#include <cuda_fp16.h>
#include <cstdint>

#define NN 20000
#define EE 320000
#define DD 128
#define LL 5
#define EVV 5
#define BN_EPS 1e-5f
#define MPAD 20096

// ---------------- device scratch (no allocation allowed) ----------------
__device__ uint4 g_hh[NN * 32];        // fp16 h, [node][fg]: {t1 f0..3, t2 f0..3}
__device__ float g_Y1[NN * DD];
__device__ float g_Y2[NN * DD];
__device__ __nv_bfloat16 g_A1hi[MPAD * DD];
__device__ __nv_bfloat16 g_A1lo[MPAD * DD];
__device__ __nv_bfloat16 g_A2hi[MPAD * DD];
__device__ __nv_bfloat16 g_A2lo[MPAD * DD];
__device__ __nv_bfloat16 g_Whi[2 * LL * DD * DD];
__device__ __nv_bfloat16 g_Wlo[2 * LL * DD * DD];
__device__ int   g_deg[NN];
__device__ int   g_off[NN + 1];
__device__ int   g_cur[NN];
__device__ int   g_pack[EE];     // (src << 3) | attr
__device__ float g_sumL[LL * 2 * DD];
__device__ float g_sqL[LL * 2 * DD];

// ---------------- PTX helpers ----------------
__device__ __forceinline__ uint32_t smem_u32(const void* p) {
    uint32_t a;
    asm("{ .reg .u64 t; cvta.to.shared.u64 t, %1; cvt.u32.u64 %0, t; }" : "=r"(a) : "l"(p));
    return a;
}
__device__ __forceinline__ void ldsm4(uint32_t* r, uint32_t addr) {
    asm volatile("ldmatrix.sync.aligned.m8n8.x4.shared.b16 {%0,%1,%2,%3}, [%4];"
                 : "=r"(r[0]), "=r"(r[1]), "=r"(r[2]), "=r"(r[3]) : "r"(addr));
}
__device__ __forceinline__ void mma16816(float* d, const uint32_t* a, const uint32_t* b) {
    asm volatile(
        "mma.sync.aligned.m16n8k16.row.col.f32.bf16.bf16.f32 "
        "{%0,%1,%2,%3}, {%4,%5,%6,%7}, {%8,%9}, {%0,%1,%2,%3};"
        : "+f"(d[0]), "+f"(d[1]), "+f"(d[2]), "+f"(d[3])
        : "r"(a[0]), "r"(a[1]), "r"(a[2]), "r"(a[3]), "r"(b[0]), "r"(b[1]));
}
__device__ __forceinline__ void cp16(uint32_t dst, const void* src) {
    asm volatile("cp.async.cg.shared.global [%0], [%1], 16;" :: "r"(dst), "l"(src));
}
__device__ __forceinline__ void cp_commit_wait() {
    asm volatile("cp.async.commit_group;" ::: "memory");
    asm volatile("cp.async.wait_group 0;" ::: "memory");
}

// ---------------- small vector helpers ----------------
__device__ __forceinline__ float4 f4relu(float4 a) {
    return make_float4(fmaxf(a.x, 0.f), fmaxf(a.y, 0.f), fmaxf(a.z, 0.f), fmaxf(a.w, 0.f));
}
__device__ __forceinline__ float4 f4s(float s, float4 a) {
    return make_float4(s * a.x, s * a.y, s * a.z, s * a.w);
}
__device__ __forceinline__ uint32_t packh2(float a, float b) {
    __half2 h = __floats2half2_rn(a, b);
    return *(uint32_t*)&h;
}
__device__ __forceinline__ __half2 u2h2(uint32_t u) { return *(__half2*)&u; }
// bf16 hi/lo split of a float4
__device__ __forceinline__ void split4(float4 r, uint2* hi, uint2* lo) {
    __nv_bfloat16 hx = __float2bfloat16(r.x), hy = __float2bfloat16(r.y);
    __nv_bfloat16 hz = __float2bfloat16(r.z), hw = __float2bfloat16(r.w);
    __nv_bfloat16 lx = __float2bfloat16(r.x - __bfloat162float(hx));
    __nv_bfloat16 ly = __float2bfloat16(r.y - __bfloat162float(hy));
    __nv_bfloat16 lz = __float2bfloat16(r.z - __bfloat162float(hz));
    __nv_bfloat16 lw = __float2bfloat16(r.w - __bfloat162float(hw));
    hi->x = (uint32_t)__bfloat16_as_ushort(hx) | ((uint32_t)__bfloat16_as_ushort(hy) << 16);
    hi->y = (uint32_t)__bfloat16_as_ushort(hz) | ((uint32_t)__bfloat16_as_ushort(hw) << 16);
    lo->x = (uint32_t)__bfloat16_as_ushort(lx) | ((uint32_t)__bfloat16_as_ushort(ly) << 16);
    lo->y = (uint32_t)__bfloat16_as_ushort(lz) | ((uint32_t)__bfloat16_as_ushort(lw) << 16);
}

// ---------------- CSR build ----------------
__global__ void k_hist(const int* __restrict__ ei) {
    int e = blockIdx.x * blockDim.x + threadIdx.x;
    if (e < EE) atomicAdd(&g_deg[ei[EE + e]], 1);
}

__global__ void k_scan() {
    __shared__ int wsum[32];
    __shared__ int carry;
    int tid = threadIdx.x, lane = tid & 31, w = tid >> 5;
    if (tid == 0) { carry = 0; g_off[0] = 0; }
    __syncthreads();
    for (int base = 0; base < NN; base += 1024) {
        int i = base + tid;
        int v = (i < NN) ? g_deg[i] : 0;
        int x = v;
#pragma unroll
        for (int o = 1; o < 32; o <<= 1) {
            int y = __shfl_up_sync(0xffffffffu, x, o);
            if (lane >= o) x += y;
        }
        if (lane == 31) wsum[w] = x;
        __syncthreads();
        if (w == 0) {
            int s = wsum[lane];
#pragma unroll
            for (int o = 1; o < 32; o <<= 1) {
                int y = __shfl_up_sync(0xffffffffu, s, o);
                if (lane >= o) s += y;
            }
            wsum[lane] = s;
        }
        __syncthreads();
        int incl = x + (w ? wsum[w - 1] : 0) + carry;
        if (i < NN) { g_off[i + 1] = incl; g_cur[i] = incl - v; }
        __syncthreads();
        if (tid == 1023) carry = incl;
        __syncthreads();
    }
}

__global__ void k_scatter(const int* __restrict__ ei, const int* __restrict__ ea) {
    int e = blockIdx.x * blockDim.x + threadIdx.x;
    if (e < EE) {
        int d = ei[EE + e];
        int p = atomicAdd(&g_cur[d], 1);
        g_pack[p] = (ei[e] << 3) | ea[e];
    }
}

// ---------------- merged prologue: deg/stat zero + W bf16 split + encode -----
__global__ void k_prep(const float* __restrict__ Wfull, const int* __restrict__ x,
                       const float* __restrict__ ne1, const float* __restrict__ ne2) {
    int i = blockIdx.x * blockDim.x + threadIdx.x;
    if (i < NN) g_deg[i] = 0;
    if (i < LL * 2 * DD) { g_sumL[i] = 0.f; g_sqL[i] = 0.f; }
    if (i < 2 * LL * DD * DD) {
        float v = Wfull[i];
        __nv_bfloat16 h = __float2bfloat16(v);
        g_Whi[i] = h;
        g_Wlo[i] = __float2bfloat16(v - __bfloat162float(h));
    }
    if (i < NN * 32) {
        int n = i >> 5, c = i & 31;
        int xv = x[n];
        float4 a = ((const float4*)ne1)[xv * 32 + c];
        float4 b = ((const float4*)ne2)[xv * 32 + c];
        uint4 u;
        u.x = packh2(a.x, a.y); u.y = packh2(a.z, a.w);
        u.z = packh2(b.x, b.y); u.w = packh2(b.z, b.w);
        g_hh[n * 32 + c] = u;
    }
}

// ---------------- gather aggregation: half2 msg math, fp32 accumulate --------
// Inner body: one edge's message into the fp32 accumulators
#define AGG_EDGE(U, T) do {                                            \
    __half2 m0 = __hmax2(__hadd2(u2h2((U).x), u2h2((T).x)), zero2);    \
    __half2 m1 = __hmax2(__hadd2(u2h2((U).y), u2h2((T).y)), zero2);    \
    __half2 m2 = __hmax2(__hadd2(u2h2((U).z), u2h2((T).z)), zero2);    \
    __half2 m3 = __hmax2(__hadd2(u2h2((U).w), u2h2((T).w)), zero2);    \
    float2 f0 = __half22float2(m0);                                    \
    float2 f1 = __half22float2(m1);                                    \
    float2 f2 = __half22float2(m2);                                    \
    float2 f3 = __half22float2(m3);                                    \
    acc1.x += f0.x; acc1.y += f0.y; acc1.z += f1.x; acc1.w += f1.y;    \
    acc2.x += f2.x; acc2.y += f2.y; acc2.z += f3.x; acc2.w += f3.y;    \
} while (0)

__global__ __launch_bounds__(512, 2) void k_aggregate(const float* __restrict__ eemb,
                                                      const float* __restrict__ eps_ptr,
                                                      int layer) {
    __shared__ uint4 s_eth[EVV * 32];   // fp16 edge tables, interleaved like g_hh
    int tid = threadIdx.x;
    const float* et1 = eemb + (0 * LL + layer) * EVV * DD;
    const float* et2 = eemb + (1 * LL + layer) * EVV * DD;
    if (tid < EVV * 32) {
        float4 t1 = ((const float4*)et1)[tid];
        float4 t2 = ((const float4*)et2)[tid];
        uint4 u;
        u.x = packh2(t1.x, t1.y); u.y = packh2(t1.z, t1.w);
        u.z = packh2(t2.x, t2.y); u.w = packh2(t2.z, t2.w);
        s_eth[tid] = u;
    }
    __syncthreads();

    int warp = tid >> 5, lane = tid & 31;
    int n = blockIdx.x * 16 + warp;           // grid 1250 * 16 = 20000 exactly

    int beg = g_off[n], deg = g_off[n + 1] - beg;
    float4 acc1 = make_float4(0.f, 0.f, 0.f, 0.f);
    float4 acc2 = make_float4(0.f, 0.f, 0.f, 0.f);
    const __half2 zero2 = __floats2half2_rn(0.f, 0.f);

    for (int base = 0; base < deg; base += 32) {
        int idx = base + lane;
        int pk = (idx < deg) ? __ldg(&g_pack[beg + idx]) : 0;
        int cnt = min(32, deg - base);
        int k = 0;
        // 8-wide groups: 8 independent gathers in flight
        for (; k + 8 <= cnt; k += 8) {
            int pa[8];
            uint4 u[8];
#pragma unroll
            for (int j = 0; j < 8; j++) pa[j] = __shfl_sync(0xffffffffu, pk, k + j);
#pragma unroll
            for (int j = 0; j < 8; j++)
                u[j] = __ldg(&g_hh[(pa[j] >> 3) * 32 + lane]);
#pragma unroll
            for (int j = 0; j < 8; j++) {
                uint4 t = s_eth[(pa[j] & 7) * 32 + lane];
                AGG_EDGE(u[j], t);
            }
        }
        // 4-wide remainder
        for (; k + 4 <= cnt; k += 4) {
            int pa[4];
            uint4 u[4];
#pragma unroll
            for (int j = 0; j < 4; j++) pa[j] = __shfl_sync(0xffffffffu, pk, k + j);
#pragma unroll
            for (int j = 0; j < 4; j++)
                u[j] = __ldg(&g_hh[(pa[j] >> 3) * 32 + lane]);
#pragma unroll
            for (int j = 0; j < 4; j++) {
                uint4 t = s_eth[(pa[j] & 7) * 32 + lane];
                AGG_EDGE(u[j], t);
            }
        }
        // scalar remainder
        for (; k < cnt; k++) {
            int p = __shfl_sync(0xffffffffu, pk, k);
            uint4 u = __ldg(&g_hh[(p >> 3) * 32 + lane]);
            uint4 t = s_eth[(p & 7) * 32 + lane];
            AGG_EDGE(u, t);
        }
    }
    float e1 = 1.f + eps_ptr[layer];
    float e2 = 1.f + eps_ptr[LL + layer];
    uint4 u = __ldg(&g_hh[n * 32 + lane]);
    float2 fa = __half22float2(u2h2(u.x));
    float2 fb = __half22float2(u2h2(u.y));
    float2 fc = __half22float2(u2h2(u.z));
    float2 fd = __half22float2(u2h2(u.w));
    float4 r1 = make_float4(fmaf(e1, fa.x, acc1.x), fmaf(e1, fa.y, acc1.y),
                            fmaf(e1, fb.x, acc1.z), fmaf(e1, fb.y, acc1.w));
    float4 r2 = make_float4(fmaf(e2, fc.x, acc2.x), fmaf(e2, fc.y, acc2.y),
                            fmaf(e2, fd.x, acc2.z), fmaf(e2, fd.y, acc2.w));

    uint2 hi, lo;
    split4(r1, &hi, &lo);
    *(uint2*)&g_A1hi[n * DD + lane * 4] = hi;
    *(uint2*)&g_A1lo[n * DD + lane * 4] = lo;
    split4(r2, &hi, &lo);
    *(uint2*)&g_A2hi[n * DD + lane * 4] = hi;
    *(uint2*)&g_A2lo[n * DD + lane * 4] = lo;
}

// ---------------- HMMA GEMM: Y = A @ W^T + b (bf16 hi/lo x3, fp32 acc) -------
// BM=64 -> SMEM 96KB: Ahi 16K | Alo 16K | Whi 32K | Wlo 32K  (2 blocks/SM)
#define SA_HI 0
#define SA_LO 16384
#define SW_HI 32768
#define SW_LO 65536
#define SM_GEMM_TOTAL 98304

__global__ __launch_bounds__(256, 2) void k_gemm_tc(const float* __restrict__ bfull,
                                                    int layer) {
    extern __shared__ char smem[];
    uint32_t sbase = smem_u32(smem);
    int tid = threadIdx.x;
    int wid = tid >> 5, lane = tid & 31;

    int t = blockIdx.y;
    const __nv_bfloat16* Ahi = t ? g_A2hi : g_A1hi;
    const __nv_bfloat16* Alo = t ? g_A2lo : g_A1lo;
    const __nv_bfloat16* Whi = g_Whi + (t * LL + layer) * DD * DD;
    const __nv_bfloat16* Wlo = g_Wlo + (t * LL + layer) * DD * DD;
    float* Y = t ? g_Y2 : g_Y1;
    const float* bp = bfull + (t * LL + layer) * DD;
    int m0 = blockIdx.x * 64;

    for (int i = tid; i < 2048; i += 256) {
        int half = i >> 10;
        int idx = i & 1023;
        int row = idx >> 4, ch = idx & 15;
        uint32_t so = (uint32_t)row * 256u + (uint32_t)((ch ^ (row & 7)) << 4);
        const __nv_bfloat16* src = (half ? Alo : Ahi) + (size_t)(m0 + row) * DD;
        cp16(sbase + (half ? SA_LO : SA_HI) + so, (const char*)src + ch * 16);
    }
    for (int i = tid; i < 4096; i += 256) {
        int half = i >> 11;
        int idx = i & 2047;
        int row = idx >> 4, ch = idx & 15;
        uint32_t so = (uint32_t)row * 256u + (uint32_t)((ch ^ (row & 7)) << 4);
        const __nv_bfloat16* src = (half ? Wlo : Whi) + (size_t)row * DD;
        cp16(sbase + (half ? SW_LO : SW_HI) + so, (const char*)src + ch * 16);
    }
    cp_commit_wait();
    __syncthreads();

    int wm = wid & 1, wn = wid >> 1;
    int grp = lane >> 3, r8 = lane & 7;
    int a_row0 = wm * 32 + (grp & 1) * 8 + r8;
    int b_row0 = wn * 32 + (grp >> 1) * 8 + r8;
    int kselA = grp >> 1;
    int kselB = grp & 1;

    float acc[2][4][4];
#pragma unroll
    for (int i = 0; i < 2; i++)
#pragma unroll
        for (int j = 0; j < 4; j++)
#pragma unroll
            for (int q = 0; q < 4; q++) acc[i][j][q] = 0.f;

#pragma unroll
    for (int p = 0; p < 3; p++) {
        uint32_t Ab = sbase + ((p == 2) ? SA_LO : SA_HI);
        uint32_t Bb = sbase + ((p == 1) ? SW_LO : SW_HI);
#pragma unroll
        for (int ks = 0; ks < 8; ks++) {
            uint32_t af[2][4], bf[2][4];
            uint32_t aoff = (uint32_t)(((ks * 2 + kselA) ^ r8) << 4);
            ldsm4(af[0], Ab + (uint32_t)a_row0 * 256u + aoff);
            ldsm4(af[1], Ab + (uint32_t)(a_row0 + 16) * 256u + aoff);
            uint32_t boff = (uint32_t)(((ks * 2 + kselB) ^ r8) << 4);
            ldsm4(bf[0], Bb + (uint32_t)b_row0 * 256u + boff);
            ldsm4(bf[1], Bb + (uint32_t)(b_row0 + 16) * 256u + boff);
#pragma unroll
            for (int i = 0; i < 2; i++)
#pragma unroll
                for (int j = 0; j < 4; j++)
                    mma16816(acc[i][j], af[i], &bf[j >> 1][(j & 1) * 2]);
        }
    }

    float* gsum = g_sumL + layer * 2 * DD + t * DD;
    float* gsq = g_sqL + layer * 2 * DD + t * DD;
    int qr = lane >> 2, qc = lane & 3;
#pragma unroll
    for (int j = 0; j < 4; j++) {
        int c0 = wn * 32 + j * 8 + qc * 2;
        float bb0 = bp[c0], bb1 = bp[c0 + 1];
        float s0 = 0.f, s1 = 0.f, q0 = 0.f, q1 = 0.f;
#pragma unroll
        for (int i = 0; i < 2; i++) {
#pragma unroll
            for (int h = 0; h < 2; h++) {
                int m = m0 + wm * 32 + i * 16 + qr + h * 8;
                float v0 = acc[i][j][h * 2 + 0] + bb0;
                float v1 = acc[i][j][h * 2 + 1] + bb1;
                if (m < NN) {
                    *(float2*)&Y[m * DD + c0] = make_float2(v0, v1);
                    s0 += v0; s1 += v1;
                    q0 += v0 * v0; q1 += v1 * v1;
                }
            }
        }
#pragma unroll
        for (int off = 4; off < 32; off <<= 1) {
            s0 += __shfl_xor_sync(0xffffffffu, s0, off);
            s1 += __shfl_xor_sync(0xffffffffu, s1, off);
            q0 += __shfl_xor_sync(0xffffffffu, q0, off);
            q1 += __shfl_xor_sync(0xffffffffu, q1, off);
        }
        if (qr == 0) {
            atomicAdd(&gsum[c0], s0);
            atomicAdd(&gsum[c0 + 1], s1);
            atomicAdd(&gsq[c0], q0);
            atomicAdd(&gsq[c0 + 1], q1);
        }
    }
}

// ---------------- BN + relu + cross-stitch (per node) ----------------
__global__ void k_bn_cross(const float* __restrict__ gam,
                           const float* __restrict__ bet,
                           const float* __restrict__ cu,
                           int layer, int last, float* __restrict__ out) {
    int idx = blockIdx.x * blockDim.x + threadIdx.x;
    if (idx >= NN * 32) return;
    int n = idx >> 5, c4 = idx & 31;
    int f = c4 * 4;
    const float inv = 1.f / (float)NN;
    const float* gsum = g_sumL + layer * 2 * DD;
    const float* gsq = g_sqL + layer * 2 * DD;

    float4 s1 = *(const float4*)&gsum[f];
    float4 q1 = *(const float4*)&gsq[f];
    float4 s2 = *(const float4*)&gsum[DD + f];
    float4 q2 = *(const float4*)&gsq[DD + f];

    float4 mu1 = f4s(inv, s1), mu2 = f4s(inv, s2);
    float4 rs1 = make_float4(rsqrtf(q1.x * inv - mu1.x * mu1.x + BN_EPS),
                             rsqrtf(q1.y * inv - mu1.y * mu1.y + BN_EPS),
                             rsqrtf(q1.z * inv - mu1.z * mu1.z + BN_EPS),
                             rsqrtf(q1.w * inv - mu1.w * mu1.w + BN_EPS));
    float4 rs2 = make_float4(rsqrtf(q2.x * inv - mu2.x * mu2.x + BN_EPS),
                             rsqrtf(q2.y * inv - mu2.y * mu2.y + BN_EPS),
                             rsqrtf(q2.z * inv - mu2.z * mu2.z + BN_EPS),
                             rsqrtf(q2.w * inv - mu2.w * mu2.w + BN_EPS));

    float4 g1 = *(const float4*)&gam[(0 * LL + layer) * DD + f];
    float4 b1 = *(const float4*)&bet[(0 * LL + layer) * DD + f];
    float4 g2 = *(const float4*)&gam[(1 * LL + layer) * DD + f];
    float4 b2 = *(const float4*)&bet[(1 * LL + layer) * DD + f];

    float4 y1 = ((const float4*)g_Y1)[n * 32 + c4];
    float4 y2 = ((const float4*)g_Y2)[n * 32 + c4];

    y1.x = (y1.x - mu1.x) * rs1.x * g1.x + b1.x;
    y1.y = (y1.y - mu1.y) * rs1.y * g1.y + b1.y;
    y1.z = (y1.z - mu1.z) * rs1.z * g1.z + b1.z;
    y1.w = (y1.w - mu1.w) * rs1.w * g1.w + b1.w;
    y2.x = (y2.x - mu2.x) * rs2.x * g2.x + b2.x;
    y2.y = (y2.y - mu2.y) * rs2.y * g2.y + b2.y;
    y2.z = (y2.z - mu2.z) * rs2.z * g2.z + b2.z;
    y2.w = (y2.w - mu2.w) * rs2.w * g2.w + b2.w;

    if (!last) {
        y1 = f4relu(y1);
        y2 = f4relu(y2);
    }

    float c00 = cu[layer * 4 + 0], c01 = cu[layer * 4 + 1];
    float c10 = cu[layer * 4 + 2], c11 = cu[layer * 4 + 3];

    float4 n1 = make_float4(c00 * y1.x + c01 * y2.x, c00 * y1.y + c01 * y2.y,
                            c00 * y1.z + c01 * y2.z, c00 * y1.w + c01 * y2.w);
    float4 n2 = make_float4(c10 * n1.x + c11 * y2.x, c10 * n1.y + c11 * y2.y,
                            c10 * n1.z + c11 * y2.z, c10 * n1.w + c11 * y2.w);

    if (last) {
        ((float4*)out)[n * 32 + c4] = n1;
        ((float4*)out)[NN * 32 + n * 32 + c4] = n2;
    } else {
        uint4 u;
        u.x = packh2(n1.x, n1.y); u.y = packh2(n1.z, n1.w);
        u.z = packh2(n2.x, n2.y); u.w = packh2(n2.z, n2.w);
        g_hh[n * 32 + c4] = u;
    }
}

// ---------------- launch ----------------
extern "C" void kernel_launch(void* const* d_in, const int* in_sizes, int n_in,
                              void* d_out, int out_size) {
    const int* x = (const int*)d_in[0];
    const int* ei = (const int*)d_in[1];
    const int* ea = (const int*)d_in[2];
    const float* ne1 = (const float*)d_in[3];
    const float* ne2 = (const float*)d_in[4];
    const float* eemb = (const float*)d_in[5];
    const float* eps = (const float*)d_in[6];
    const float* W = (const float*)d_in[7];
    const float* b = (const float*)d_in[8];
    const float* gam = (const float*)d_in[9];
    const float* bet = (const float*)d_in[10];
    const float* cu = (const float*)d_in[11];
    float* out = (float*)d_out;

    static int smem_set = 0;
    if (!smem_set) {
        cudaFuncSetAttribute(k_gemm_tc, cudaFuncAttributeMaxDynamicSharedMemorySize,
                             SM_GEMM_TOTAL);
        smem_set = 1;
    }

    k_prep<<<(NN * 32 + 255) / 256, 256>>>(W, x, ne1, ne2);
    k_hist<<<(EE + 255) / 256, 256>>>(ei);
    k_scan<<<1, 1024>>>();
    k_scatter<<<(EE + 255) / 256, 256>>>(ei, ea);

    for (int l = 0; l < LL; l++) {
        k_aggregate<<<NN / 16, 512>>>(eemb, eps, l);
        dim3 gg((NN + 63) / 64, 2);
        k_gemm_tc<<<gg, 256, SM_GEMM_TOTAL>>>(b, l);
        k_bn_cross<<<(NN * 32 + 255) / 256, 256>>>(gam, bet, cu, l, (l == LL - 1) ? 1 : 0, out);
    }
}

// round 16
// speedup vs baseline: 1.5888x; 1.0349x over previous
#include <cuda_runtime.h>
#include <cuda_bf16.h>
#include <cuda_fp16.h>
#include <cstdint>

#define NN 20000
#define EE 320000
#define DD 128
#define LL 5
#define EVV 5
#define BN_EPS 1e-5f
#define MPAD 20096

// ---------------- device scratch (no allocation allowed) ----------------
__device__ uint4 g_hh[NN * 32];        // fp16 h, [node][fg]: {t1 f0..3, t2 f0..3}
__device__ float g_Y1[NN * DD];
__device__ float g_Y2[NN * DD];
__device__ __nv_bfloat16 g_A1hi[MPAD * DD];
__device__ __nv_bfloat16 g_A1lo[MPAD * DD];
__device__ __nv_bfloat16 g_A2hi[MPAD * DD];
__device__ __nv_bfloat16 g_A2lo[MPAD * DD];
__device__ __nv_bfloat16 g_Whi[2 * LL * DD * DD];
__device__ __nv_bfloat16 g_Wlo[2 * LL * DD * DD];
__device__ int   g_deg[NN];
__device__ int   g_off[NN + 1];
__device__ int   g_cur[NN];
__device__ int   g_pack[EE];     // (src << 3) | attr
__device__ float g_sumL[LL * 2 * DD];
__device__ float g_sqL[LL * 2 * DD];

// ---------------- PTX helpers ----------------
__device__ __forceinline__ void grid_dep_trigger() {
    asm volatile("griddepcontrol.launch_dependents;" ::: "memory");
}
__device__ __forceinline__ void grid_dep_wait() {
    asm volatile("griddepcontrol.wait;" ::: "memory");
}
__device__ __forceinline__ uint32_t smem_u32(const void* p) {
    uint32_t a;
    asm("{ .reg .u64 t; cvta.to.shared.u64 t, %1; cvt.u32.u64 %0, t; }" : "=r"(a) : "l"(p));
    return a;
}
__device__ __forceinline__ void ldsm4(uint32_t* r, uint32_t addr) {
    asm volatile("ldmatrix.sync.aligned.m8n8.x4.shared.b16 {%0,%1,%2,%3}, [%4];"
                 : "=r"(r[0]), "=r"(r[1]), "=r"(r[2]), "=r"(r[3]) : "r"(addr));
}
__device__ __forceinline__ void mma16816(float* d, const uint32_t* a, const uint32_t* b) {
    asm volatile(
        "mma.sync.aligned.m16n8k16.row.col.f32.bf16.bf16.f32 "
        "{%0,%1,%2,%3}, {%4,%5,%6,%7}, {%8,%9}, {%0,%1,%2,%3};"
        : "+f"(d[0]), "+f"(d[1]), "+f"(d[2]), "+f"(d[3])
        : "r"(a[0]), "r"(a[1]), "r"(a[2]), "r"(a[3]), "r"(b[0]), "r"(b[1]));
}
__device__ __forceinline__ void cp16(uint32_t dst, const void* src) {
    asm volatile("cp.async.cg.shared.global [%0], [%1], 16;" :: "r"(dst), "l"(src));
}
__device__ __forceinline__ void cp_commit_wait() {
    asm volatile("cp.async.commit_group;" ::: "memory");
    asm volatile("cp.async.wait_group 0;" ::: "memory");
}

// ---------------- small vector helpers ----------------
__device__ __forceinline__ float4 f4relu(float4 a) {
    return make_float4(fmaxf(a.x, 0.f), fmaxf(a.y, 0.f), fmaxf(a.z, 0.f), fmaxf(a.w, 0.f));
}
__device__ __forceinline__ float4 f4s(float s, float4 a) {
    return make_float4(s * a.x, s * a.y, s * a.z, s * a.w);
}
__device__ __forceinline__ uint32_t packh2(float a, float b) {
    __half2 h = __floats2half2_rn(a, b);
    return *(uint32_t*)&h;
}
__device__ __forceinline__ __half2 u2h2(uint32_t u) { return *(__half2*)&u; }
__device__ __forceinline__ void split4(float4 r, uint2* hi, uint2* lo) {
    __nv_bfloat16 hx = __float2bfloat16(r.x), hy = __float2bfloat16(r.y);
    __nv_bfloat16 hz = __float2bfloat16(r.z), hw = __float2bfloat16(r.w);
    __nv_bfloat16 lx = __float2bfloat16(r.x - __bfloat162float(hx));
    __nv_bfloat16 ly = __float2bfloat16(r.y - __bfloat162float(hy));
    __nv_bfloat16 lz = __float2bfloat16(r.z - __bfloat162float(hz));
    __nv_bfloat16 lw = __float2bfloat16(r.w - __bfloat162float(hw));
    hi->x = (uint32_t)__bfloat16_as_ushort(hx) | ((uint32_t)__bfloat16_as_ushort(hy) << 16);
    hi->y = (uint32_t)__bfloat16_as_ushort(hz) | ((uint32_t)__bfloat16_as_ushort(hw) << 16);
    lo->x = (uint32_t)__bfloat16_as_ushort(lx) | ((uint32_t)__bfloat16_as_ushort(ly) << 16);
    lo->y = (uint32_t)__bfloat16_as_ushort(lz) | ((uint32_t)__bfloat16_as_ushort(lw) << 16);
}

// ---------------- CSR build ----------------
__global__ void k_hist(const int* __restrict__ ei) {
    grid_dep_trigger();
    grid_dep_wait();            // g_deg zeroed by k_prep
    int e = blockIdx.x * blockDim.x + threadIdx.x;
    if (e < EE) atomicAdd(&g_deg[ei[EE + e]], 1);
}

__global__ void k_scan() {
    grid_dep_trigger();
    grid_dep_wait();            // g_deg from k_hist
    __shared__ int wsum[32];
    __shared__ int carry;
    int tid = threadIdx.x, lane = tid & 31, w = tid >> 5;
    if (tid == 0) { carry = 0; g_off[0] = 0; }
    __syncthreads();
    for (int base = 0; base < NN; base += 1024) {
        int i = base + tid;
        int v = (i < NN) ? g_deg[i] : 0;
        int x = v;
#pragma unroll
        for (int o = 1; o < 32; o <<= 1) {
            int y = __shfl_up_sync(0xffffffffu, x, o);
            if (lane >= o) x += y;
        }
        if (lane == 31) wsum[w] = x;
        __syncthreads();
        if (w == 0) {
            int s = wsum[lane];
#pragma unroll
            for (int o = 1; o < 32; o <<= 1) {
                int y = __shfl_up_sync(0xffffffffu, s, o);
                if (lane >= o) s += y;
            }
            wsum[lane] = s;
        }
        __syncthreads();
        int incl = x + (w ? wsum[w - 1] : 0) + carry;
        if (i < NN) { g_off[i + 1] = incl; g_cur[i] = incl - v; }
        __syncthreads();
        if (tid == 1023) carry = incl;
        __syncthreads();
    }
}

__global__ void k_scatter(const int* __restrict__ ei, const int* __restrict__ ea) {
    grid_dep_trigger();
    grid_dep_wait();            // g_cur from k_scan
    int e = blockIdx.x * blockDim.x + threadIdx.x;
    if (e < EE) {
        int d = ei[EE + e];
        int p = atomicAdd(&g_cur[d], 1);
        g_pack[p] = (ei[e] << 3) | ea[e];
    }
}

// ---------------- merged prologue: deg/stat zero + W bf16 split + encode -----
// NOTE: no early trigger here — dependents launch only at completion, which
// guarantees all k_prep outputs (g_Whi/g_Wlo/g_hh/g_deg/stats) are visible to
// every later kernel even BEFORE its griddepcontrol.wait.
__global__ void k_prep(const float* __restrict__ Wfull, const int* __restrict__ x,
                       const float* __restrict__ ne1, const float* __restrict__ ne2) {
    int i = blockIdx.x * blockDim.x + threadIdx.x;
    if (i < NN) g_deg[i] = 0;
    if (i < LL * 2 * DD) { g_sumL[i] = 0.f; g_sqL[i] = 0.f; }
    if (i < 2 * LL * DD * DD) {
        float v = Wfull[i];
        __nv_bfloat16 h = __float2bfloat16(v);
        g_Whi[i] = h;
        g_Wlo[i] = __float2bfloat16(v - __bfloat162float(h));
    }
    if (i < NN * 32) {
        int n = i >> 5, c = i & 31;
        int xv = x[n];
        float4 a = ((const float4*)ne1)[xv * 32 + c];
        float4 b = ((const float4*)ne2)[xv * 32 + c];
        uint4 u;
        u.x = packh2(a.x, a.y); u.y = packh2(a.z, a.w);
        u.z = packh2(b.x, b.y); u.w = packh2(b.z, b.w);
        g_hh[n * 32 + c] = u;
    }
}

// ---------------- gather aggregation: half2 msg math, fp32 accumulate --------
#define AGG_EDGE(U, T) do {                                            \
    __half2 m0 = __hmax2(__hadd2(u2h2((U).x), u2h2((T).x)), zero2);    \
    __half2 m1 = __hmax2(__hadd2(u2h2((U).y), u2h2((T).y)), zero2);    \
    __half2 m2 = __hmax2(__hadd2(u2h2((U).z), u2h2((T).z)), zero2);    \
    __half2 m3 = __hmax2(__hadd2(u2h2((U).w), u2h2((T).w)), zero2);    \
    float2 f0 = __half22float2(m0);                                    \
    float2 f1 = __half22float2(m1);                                    \
    float2 f2 = __half22float2(m2);                                    \
    float2 f3 = __half22float2(m3);                                    \
    acc1.x += f0.x; acc1.y += f0.y; acc1.z += f1.x; acc1.w += f1.y;    \
    acc2.x += f2.x; acc2.y += f2.y; acc2.z += f3.x; acc2.w += f3.y;    \
} while (0)

__global__ __launch_bounds__(512, 2) void k_aggregate(const float* __restrict__ eemb,
                                                      const float* __restrict__ eps_ptr,
                                                      int layer) {
    grid_dep_trigger();
    __shared__ uint4 s_eth[EVV * 32];   // fp16 edge tables (harness inputs: pre-wait OK)
    int tid = threadIdx.x;
    const float* et1 = eemb + (0 * LL + layer) * EVV * DD;
    const float* et2 = eemb + (1 * LL + layer) * EVV * DD;
    if (tid < EVV * 32) {
        float4 t1 = ((const float4*)et1)[tid];
        float4 t2 = ((const float4*)et2)[tid];
        uint4 u;
        u.x = packh2(t1.x, t1.y); u.y = packh2(t1.z, t1.w);
        u.z = packh2(t2.x, t2.y); u.w = packh2(t2.z, t2.w);
        s_eth[tid] = u;
    }
    float e1 = 1.f + eps_ptr[layer];
    float e2 = 1.f + eps_ptr[LL + layer];
    grid_dep_wait();            // g_off/g_pack (CSR) and g_hh (prev bn_cross)
    __syncthreads();

    int warp = tid >> 5, lane = tid & 31;
    int n = blockIdx.x * 16 + warp;           // grid 1250 * 16 = 20000 exactly

    int beg = g_off[n], deg = g_off[n + 1] - beg;
    float4 acc1 = make_float4(0.f, 0.f, 0.f, 0.f);
    float4 acc2 = make_float4(0.f, 0.f, 0.f, 0.f);
    const __half2 zero2 = __floats2half2_rn(0.f, 0.f);

    for (int base = 0; base < deg; base += 32) {
        int idx = base + lane;
        int pk = (idx < deg) ? __ldg(&g_pack[beg + idx]) : 0;
        int cnt = min(32, deg - base);
        int k = 0;
        for (; k + 8 <= cnt; k += 8) {
            int pa[8];
            uint4 u[8];
#pragma unroll
            for (int j = 0; j < 8; j++) pa[j] = __shfl_sync(0xffffffffu, pk, k + j);
#pragma unroll
            for (int j = 0; j < 8; j++)
                u[j] = __ldg(&g_hh[(pa[j] >> 3) * 32 + lane]);
#pragma unroll
            for (int j = 0; j < 8; j++) {
                uint4 t = s_eth[(pa[j] & 7) * 32 + lane];
                AGG_EDGE(u[j], t);
            }
        }
        for (; k + 4 <= cnt; k += 4) {
            int pa[4];
            uint4 u[4];
#pragma unroll
            for (int j = 0; j < 4; j++) pa[j] = __shfl_sync(0xffffffffu, pk, k + j);
#pragma unroll
            for (int j = 0; j < 4; j++)
                u[j] = __ldg(&g_hh[(pa[j] >> 3) * 32 + lane]);
#pragma unroll
            for (int j = 0; j < 4; j++) {
                uint4 t = s_eth[(pa[j] & 7) * 32 + lane];
                AGG_EDGE(u[j], t);
            }
        }
        for (; k < cnt; k++) {
            int p = __shfl_sync(0xffffffffu, pk, k);
            uint4 u = __ldg(&g_hh[(p >> 3) * 32 + lane]);
            uint4 t = s_eth[(p & 7) * 32 + lane];
            AGG_EDGE(u, t);
        }
    }
    uint4 u = __ldg(&g_hh[n * 32 + lane]);
    float2 fa = __half22float2(u2h2(u.x));
    float2 fb = __half22float2(u2h2(u.y));
    float2 fc = __half22float2(u2h2(u.z));
    float2 fd = __half22float2(u2h2(u.w));
    float4 r1 = make_float4(fmaf(e1, fa.x, acc1.x), fmaf(e1, fa.y, acc1.y),
                            fmaf(e1, fb.x, acc1.z), fmaf(e1, fb.y, acc1.w));
    float4 r2 = make_float4(fmaf(e2, fc.x, acc2.x), fmaf(e2, fc.y, acc2.y),
                            fmaf(e2, fd.x, acc2.z), fmaf(e2, fd.y, acc2.w));

    uint2 hi, lo;
    split4(r1, &hi, &lo);
    *(uint2*)&g_A1hi[n * DD + lane * 4] = hi;
    *(uint2*)&g_A1lo[n * DD + lane * 4] = lo;
    split4(r2, &hi, &lo);
    *(uint2*)&g_A2hi[n * DD + lane * 4] = hi;
    *(uint2*)&g_A2lo[n * DD + lane * 4] = lo;
}

// ---------------- HMMA GEMM: Y = A @ W^T + b (bf16 hi/lo x3, fp32 acc) -------
// BM=64 -> SMEM 96KB: Ahi 16K | Alo 16K | Whi 32K | Wlo 32K  (2 blocks/SM)
#define SA_HI 0
#define SA_LO 16384
#define SW_HI 32768
#define SW_LO 65536
#define SM_GEMM_TOTAL 98304

__global__ __launch_bounds__(256, 2) void k_gemm_tc(const float* __restrict__ bfull,
                                                    int layer) {
    grid_dep_trigger();
    extern __shared__ char smem[];
    uint32_t sbase = smem_u32(smem);
    int tid = threadIdx.x;
    int wid = tid >> 5, lane = tid & 31;

    int t = blockIdx.y;
    const __nv_bfloat16* Ahi = t ? g_A2hi : g_A1hi;
    const __nv_bfloat16* Alo = t ? g_A2lo : g_A1lo;
    const __nv_bfloat16* Whi = g_Whi + (t * LL + layer) * DD * DD;
    const __nv_bfloat16* Wlo = g_Wlo + (t * LL + layer) * DD * DD;
    float* Y = t ? g_Y2 : g_Y1;
    const float* bp = bfull + (t * LL + layer) * DD;
    int m0 = blockIdx.x * 64;

    // W tiles are k_prep outputs: safe PRE-wait (k_prep has no early trigger).
    for (int i = tid; i < 4096; i += 256) {
        int half = i >> 11;
        int idx = i & 2047;
        int row = idx >> 4, ch = idx & 15;
        uint32_t so = (uint32_t)row * 256u + (uint32_t)((ch ^ (row & 7)) << 4);
        const __nv_bfloat16* src = (half ? Wlo : Whi) + (size_t)row * DD;
        cp16(sbase + (half ? SW_LO : SW_HI) + so, (const char*)src + ch * 16);
    }
    grid_dep_wait();            // A tiles from k_aggregate
    // A tiles post-wait
    for (int i = tid; i < 2048; i += 256) {
        int half = i >> 10;
        int idx = i & 1023;
        int row = idx >> 4, ch = idx & 15;
        uint32_t so = (uint32_t)row * 256u + (uint32_t)((ch ^ (row & 7)) << 4);
        const __nv_bfloat16* src = (half ? Alo : Ahi) + (size_t)(m0 + row) * DD;
        cp16(sbase + (half ? SA_LO : SA_HI) + so, (const char*)src + ch * 16);
    }
    cp_commit_wait();
    __syncthreads();

    int wm = wid & 1, wn = wid >> 1;
    int grp = lane >> 3, r8 = lane & 7;
    int a_row0 = wm * 32 + (grp & 1) * 8 + r8;
    int b_row0 = wn * 32 + (grp >> 1) * 8 + r8;
    int kselA = grp >> 1;
    int kselB = grp & 1;

    float acc[2][4][4];
#pragma unroll
    for (int i = 0; i < 2; i++)
#pragma unroll
        for (int j = 0; j < 4; j++)
#pragma unroll
            for (int q = 0; q < 4; q++) acc[i][j][q] = 0.f;

#pragma unroll
    for (int p = 0; p < 3; p++) {
        uint32_t Ab = sbase + ((p == 2) ? SA_LO : SA_HI);
        uint32_t Bb = sbase + ((p == 1) ? SW_LO : SW_HI);
#pragma unroll
        for (int ks = 0; ks < 8; ks++) {
            uint32_t af[2][4], bf[2][4];
            uint32_t aoff = (uint32_t)(((ks * 2 + kselA) ^ r8) << 4);
            ldsm4(af[0], Ab + (uint32_t)a_row0 * 256u + aoff);
            ldsm4(af[1], Ab + (uint32_t)(a_row0 + 16) * 256u + aoff);
            uint32_t boff = (uint32_t)(((ks * 2 + kselB) ^ r8) << 4);
            ldsm4(bf[0], Bb + (uint32_t)b_row0 * 256u + boff);
            ldsm4(bf[1], Bb + (uint32_t)(b_row0 + 16) * 256u + boff);
#pragma unroll
            for (int i = 0; i < 2; i++)
#pragma unroll
                for (int j = 0; j < 4; j++)
                    mma16816(acc[i][j], af[i], &bf[j >> 1][(j & 1) * 2]);
        }
    }

    float* gsum = g_sumL + layer * 2 * DD + t * DD;
    float* gsq = g_sqL + layer * 2 * DD + t * DD;
    int qr = lane >> 2, qc = lane & 3;
#pragma unroll
    for (int j = 0; j < 4; j++) {
        int c0 = wn * 32 + j * 8 + qc * 2;
        float bb0 = bp[c0], bb1 = bp[c0 + 1];
        float s0 = 0.f, s1 = 0.f, q0 = 0.f, q1 = 0.f;
#pragma unroll
        for (int i = 0; i < 2; i++) {
#pragma unroll
            for (int h = 0; h < 2; h++) {
                int m = m0 + wm * 32 + i * 16 + qr + h * 8;
                float v0 = acc[i][j][h * 2 + 0] + bb0;
                float v1 = acc[i][j][h * 2 + 1] + bb1;
                if (m < NN) {
                    *(float2*)&Y[m * DD + c0] = make_float2(v0, v1);
                    s0 += v0; s1 += v1;
                    q0 += v0 * v0; q1 += v1 * v1;
                }
            }
        }
#pragma unroll
        for (int off = 4; off < 32; off <<= 1) {
            s0 += __shfl_xor_sync(0xffffffffu, s0, off);
            s1 += __shfl_xor_sync(0xffffffffu, s1, off);
            q0 += __shfl_xor_sync(0xffffffffu, q0, off);
            q1 += __shfl_xor_sync(0xffffffffu, q1, off);
        }
        if (qr == 0) {
            atomicAdd(&gsum[c0], s0);
            atomicAdd(&gsum[c0 + 1], s1);
            atomicAdd(&gsq[c0], q0);
            atomicAdd(&gsq[c0 + 1], q1);
        }
    }
}

// ---------------- BN + relu + cross-stitch (per node) ----------------
__global__ void k_bn_cross(const float* __restrict__ gam,
                           const float* __restrict__ bet,
                           const float* __restrict__ cu,
                           int layer, int last, float* __restrict__ out) {
    grid_dep_trigger();
    int idx = blockIdx.x * blockDim.x + threadIdx.x;
    // input-only loads pre-wait
    float c00 = cu[layer * 4 + 0], c01 = cu[layer * 4 + 1];
    float c10 = cu[layer * 4 + 2], c11 = cu[layer * 4 + 3];
    grid_dep_wait();            // g_Y and BN stats from k_gemm_tc
    if (idx >= NN * 32) return;
    int n = idx >> 5, c4 = idx & 31;
    int f = c4 * 4;
    const float inv = 1.f / (float)NN;
    const float* gsum = g_sumL + layer * 2 * DD;
    const float* gsq = g_sqL + layer * 2 * DD;

    float4 s1 = *(const float4*)&gsum[f];
    float4 q1 = *(const float4*)&gsq[f];
    float4 s2 = *(const float4*)&gsum[DD + f];
    float4 q2 = *(const float4*)&gsq[DD + f];

    float4 mu1 = f4s(inv, s1), mu2 = f4s(inv, s2);
    float4 rs1 = make_float4(rsqrtf(q1.x * inv - mu1.x * mu1.x + BN_EPS),
                             rsqrtf(q1.y * inv - mu1.y * mu1.y + BN_EPS),
                             rsqrtf(q1.z * inv - mu1.z * mu1.z + BN_EPS),
                             rsqrtf(q1.w * inv - mu1.w * mu1.w + BN_EPS));
    float4 rs2 = make_float4(rsqrtf(q2.x * inv - mu2.x * mu2.x + BN_EPS),
                             rsqrtf(q2.y * inv - mu2.y * mu2.y + BN_EPS),
                             rsqrtf(q2.z * inv - mu2.z * mu2.z + BN_EPS),
                             rsqrtf(q2.w * inv - mu2.w * mu2.w + BN_EPS));

    float4 g1 = *(const float4*)&gam[(0 * LL + layer) * DD + f];
    float4 b1 = *(const float4*)&bet[(0 * LL + layer) * DD + f];
    float4 g2 = *(const float4*)&gam[(1 * LL + layer) * DD + f];
    float4 b2 = *(const float4*)&bet[(1 * LL + layer) * DD + f];

    float4 y1 = ((const float4*)g_Y1)[n * 32 + c4];
    float4 y2 = ((const float4*)g_Y2)[n * 32 + c4];

    y1.x = (y1.x - mu1.x) * rs1.x * g1.x + b1.x;
    y1.y = (y1.y - mu1.y) * rs1.y * g1.y + b1.y;
    y1.z = (y1.z - mu1.z) * rs1.z * g1.z + b1.z;
    y1.w = (y1.w - mu1.w) * rs1.w * g1.w + b1.w;
    y2.x = (y2.x - mu2.x) * rs2.x * g2.x + b2.x;
    y2.y = (y2.y - mu2.y) * rs2.y * g2.y + b2.y;
    y2.z = (y2.z - mu2.z) * rs2.z * g2.z + b2.z;
    y2.w = (y2.w - mu2.w) * rs2.w * g2.w + b2.w;

    if (!last) {
        y1 = f4relu(y1);
        y2 = f4relu(y2);
    }

    float4 n1 = make_float4(c00 * y1.x + c01 * y2.x, c00 * y1.y + c01 * y2.y,
                            c00 * y1.z + c01 * y2.z, c00 * y1.w + c01 * y2.w);
    float4 n2 = make_float4(c10 * n1.x + c11 * y2.x, c10 * n1.y + c11 * y2.y,
                            c10 * n1.z + c11 * y2.z, c10 * n1.w + c11 * y2.w);

    if (last) {
        ((float4*)out)[n * 32 + c4] = n1;
        ((float4*)out)[NN * 32 + n * 32 + c4] = n2;
    } else {
        uint4 u;
        u.x = packh2(n1.x, n1.y); u.y = packh2(n1.z, n1.w);
        u.z = packh2(n2.x, n2.y); u.w = packh2(n2.z, n2.w);
        g_hh[n * 32 + c4] = u;
    }
}

// ---------------- launch (PDL) ----------------
template <typename K, typename... Args>
static void pdl_launch(K k, dim3 grid, dim3 block, size_t smem, Args... args) {
    cudaLaunchConfig_t cfg = {};
    cfg.gridDim = grid;
    cfg.blockDim = block;
    cfg.dynamicSmemBytes = smem;
    cudaLaunchAttribute at[1];
    at[0].id = cudaLaunchAttributeProgrammaticStreamSerialization;
    at[0].val.programmaticStreamSerializationAllowed = 1;
    cfg.attrs = at;
    cfg.numAttrs = 1;
    cudaLaunchKernelEx(&cfg, k, args...);
}

extern "C" void kernel_launch(void* const* d_in, const int* in_sizes, int n_in,
                              void* d_out, int out_size) {
    const int* x = (const int*)d_in[0];
    const int* ei = (const int*)d_in[1];
    const int* ea = (const int*)d_in[2];
    const float* ne1 = (const float*)d_in[3];
    const float* ne2 = (const float*)d_in[4];
    const float* eemb = (const float*)d_in[5];
    const float* eps = (const float*)d_in[6];
    const float* W = (const float*)d_in[7];
    const float* b = (const float*)d_in[8];
    const float* gam = (const float*)d_in[9];
    const float* bet = (const float*)d_in[10];
    const float* cu = (const float*)d_in[11];
    float* out = (float*)d_out;

    static int smem_set = 0;
    if (!smem_set) {
        cudaFuncSetAttribute(k_gemm_tc, cudaFuncAttributeMaxDynamicSharedMemorySize,
                             SM_GEMM_TOTAL);
        smem_set = 1;
    }

    // k_prep: plain launch, NO early trigger (see comment at k_prep)
    k_prep<<<(NN * 32 + 255) / 256, 256>>>(W, x, ne1, ne2);
    pdl_launch(k_hist, dim3((EE + 255) / 256), dim3(256), 0, ei);
    pdl_launch(k_scan, dim3(1), dim3(1024), (size_t)0);
    pdl_launch(k_scatter, dim3((EE + 255) / 256), dim3(256), 0, ei, ea);

    for (int l = 0; l < LL; l++) {
        pdl_launch(k_aggregate, dim3(NN / 16), dim3(512), 0, eemb, eps, l);
        pdl_launch(k_gemm_tc, dim3((NN + 63) / 64, 2), dim3(256),
                   (size_t)SM_GEMM_TOTAL, b, l);
        pdl_launch(k_bn_cross, dim3((NN * 32 + 255) / 256), dim3(256), 0,
                   gam, bet, cu, l, (l == LL - 1) ? 1 : 0, out);
    }
}